// round 1
// baseline (speedup 1.0000x reference)
#include <cuda_runtime.h>
#include <math.h>

#define N_TOK   4096     // B * S
#define DMODEL  1024
#define DFF     4096
#define NHEAD   16
#define DK      64
#define SEQ     2048
#define BATCH   2

// ---------------- scratch (static device globals; no allocation) ----------------
__device__ float g_h  [N_TOK * DMODEL];   // LN output (reused for both LNs)
__device__ float g_q  [N_TOK * DMODEL];
__device__ float g_k  [N_TOK * DMODEL];
__device__ float g_v  [N_TOK * DMODEL];
__device__ float g_att[N_TOK * DMODEL];   // attention context (B,S,H,Dk) flattened
__device__ float g_x1 [N_TOK * DMODEL];   // x + attn_out @ Wo
__device__ float g_ffn[N_TOK * DFF];      // gelu(h @ W1 + b1)

// ---------------- LayerNorm: one block per row, 256 threads, float4 ----------------
__global__ void __launch_bounds__(256) ln_kernel(const float* __restrict__ x,
                                                 const float* __restrict__ gamma,
                                                 const float* __restrict__ beta,
                                                 float* __restrict__ out) {
    int row = blockIdx.x;
    int t = threadIdx.x;
    const float4 v = reinterpret_cast<const float4*>(x + (size_t)row * DMODEL)[t];
    float s  = v.x + v.y + v.z + v.w;
    float sq = v.x * v.x + v.y * v.y + v.z * v.z + v.w * v.w;
    #pragma unroll
    for (int o = 16; o; o >>= 1) {
        s  += __shfl_xor_sync(0xFFFFFFFFu, s,  o);
        sq += __shfl_xor_sync(0xFFFFFFFFu, sq, o);
    }
    __shared__ float ss[8], ssq[8];
    __shared__ float s_mean, s_rstd;
    int wid = t >> 5, lane = t & 31;
    if (lane == 0) { ss[wid] = s; ssq[wid] = sq; }
    __syncthreads();
    if (t == 0) {
        float ts = 0.f, tq = 0.f;
        #pragma unroll
        for (int i = 0; i < 8; i++) { ts += ss[i]; tq += ssq[i]; }
        float mean = ts * (1.0f / DMODEL);
        float var  = tq * (1.0f / DMODEL) - mean * mean;
        s_mean = mean;
        s_rstd = rsqrtf(var + 1e-5f);
    }
    __syncthreads();
    float mean = s_mean, rstd = s_rstd;
    float4 g4 = reinterpret_cast<const float4*>(gamma)[t];
    float4 b4 = reinterpret_cast<const float4*>(beta)[t];
    float4 o4;
    o4.x = (v.x - mean) * rstd * g4.x + b4.x;
    o4.y = (v.y - mean) * rstd * g4.y + b4.y;
    o4.z = (v.z - mean) * rstd * g4.z + b4.z;
    o4.w = (v.w - mean) * rstd * g4.w + b4.w;
    reinterpret_cast<float4*>(out + (size_t)row * DMODEL)[t] = o4;
}

// ---------------- SGEMM: C[N,M] = A[N,K] @ W[K,M] + bias (+gelu) (+res) ----------------
// 128x128 tile, BK=8, 256 threads, 8x8 accum per thread.
template<int GELU, int RES>
__global__ void __launch_bounds__(256) sgemm_kernel(const float* __restrict__ A,
                                                    const float* __restrict__ W,
                                                    const float* __restrict__ bias,
                                                    const float* __restrict__ res,
                                                    float* __restrict__ C,
                                                    int K, int M) {
    __shared__ float As[8][128];
    __shared__ float Bs[8][128];
    int t  = threadIdx.x;
    int n0 = blockIdx.y * 128;
    int m0 = blockIdx.x * 128;

    int ar = t >> 1;            // 0..127 (row within A tile)
    int ac = (t & 1) * 4;       // 0 or 4 (k offset)
    int br = t >> 5;            // 0..7  (k row of B tile)
    int bc = (t & 31) * 4;      // 0..124 (col within B tile)
    const float* Aptr = A + (size_t)(n0 + ar) * K + ac;
    const float* Wptr = W + (size_t)br * M + m0 + bc;

    int ty = (t >> 4) * 8;      // row base within tile
    int tx = (t & 15) * 8;      // col base within tile

    float acc[8][8];
    #pragma unroll
    for (int i = 0; i < 8; i++)
        #pragma unroll
        for (int j = 0; j < 8; j++) acc[i][j] = 0.f;

    for (int kt = 0; kt < K; kt += 8) {
        float4 a4 = *reinterpret_cast<const float4*>(Aptr + kt);
        float4 b4 = *reinterpret_cast<const float4*>(Wptr + (size_t)kt * M);
        As[ac + 0][ar] = a4.x;
        As[ac + 1][ar] = a4.y;
        As[ac + 2][ar] = a4.z;
        As[ac + 3][ar] = a4.w;
        *reinterpret_cast<float4*>(&Bs[br][bc]) = b4;
        __syncthreads();
        #pragma unroll
        for (int k = 0; k < 8; k++) {
            float a[8], b[8];
            *reinterpret_cast<float4*>(&a[0]) = *reinterpret_cast<float4*>(&As[k][ty]);
            *reinterpret_cast<float4*>(&a[4]) = *reinterpret_cast<float4*>(&As[k][ty + 4]);
            *reinterpret_cast<float4*>(&b[0]) = *reinterpret_cast<float4*>(&Bs[k][tx]);
            *reinterpret_cast<float4*>(&b[4]) = *reinterpret_cast<float4*>(&Bs[k][tx + 4]);
            #pragma unroll
            for (int i = 0; i < 8; i++)
                #pragma unroll
                for (int j = 0; j < 8; j++)
                    acc[i][j] = fmaf(a[i], b[j], acc[i][j]);
        }
        __syncthreads();
    }

    float bb[8];
    #pragma unroll
    for (int j = 0; j < 8; j++) bb[j] = bias[m0 + tx + j];

    #pragma unroll
    for (int i = 0; i < 8; i++) {
        size_t off = (size_t)(n0 + ty + i) * M + m0 + tx;
        float o[8];
        #pragma unroll
        for (int j = 0; j < 8; j++) {
            float c = acc[i][j] + bb[j];
            if (GELU) c = c * normcdff(c);   // exact erf-based GELU
            o[j] = c;
        }
        if (RES) {
            float4 r0 = *reinterpret_cast<const float4*>(res + off);
            float4 r1 = *reinterpret_cast<const float4*>(res + off + 4);
            o[0] += r0.x; o[1] += r0.y; o[2] += r0.z; o[3] += r0.w;
            o[4] += r1.x; o[5] += r1.y; o[6] += r1.z; o[7] += r1.w;
        }
        *reinterpret_cast<float4*>(C + off)     = make_float4(o[0], o[1], o[2], o[3]);
        *reinterpret_cast<float4*>(C + off + 4) = make_float4(o[4], o[5], o[6], o[7]);
    }
}

// ---------------- causal flash attention: warp per query, 64-key smem tiles ----------------
__global__ void __launch_bounds__(256) attn_kernel(const float* __restrict__ Q,
                                                   const float* __restrict__ K,
                                                   const float* __restrict__ V,
                                                   float* __restrict__ O) {
    __shared__ float Ks[64 * 64];
    __shared__ float Vs[64 * 64];
    int b = blockIdx.z, h = blockIdx.y;
    int q0 = blockIdx.x * 8;
    int t = threadIdx.x, wid = t >> 5, lane = t & 31;
    int q = q0 + wid;

    size_t qoff = ((size_t)(b * SEQ + q)) * DMODEL + h * DK;
    float qr0 = Q[qoff + lane];
    float qr1 = Q[qoff + 32 + lane];

    float m = -INFINITY, l = 0.f, acc0 = 0.f, acc1 = 0.f;
    int ntiles = q0 / 64 + 1;

    for (int kt = 0; kt < ntiles; kt++) {
        __syncthreads();
        #pragma unroll
        for (int i = 0; i < 4; i++) {
            int id = t + i * 256;           // 0..1023 float4 slots
            int r = id >> 4;                // key row 0..63
            int c = (id & 15) * 4;          // dim 0..60
            size_t goff = ((size_t)(b * SEQ + kt * 64 + r)) * DMODEL + h * DK + c;
            *reinterpret_cast<float4*>(&Ks[r * 64 + c]) = *reinterpret_cast<const float4*>(&K[goff]);
            *reinterpret_cast<float4*>(&Vs[r * 64 + c]) = *reinterpret_cast<const float4*>(&V[goff]);
        }
        __syncthreads();

        int jmax = min(64, q - kt * 64 + 1);
        for (int j = 0; j < jmax; j++) {
            float s = qr0 * Ks[j * 64 + lane] + qr1 * Ks[j * 64 + 32 + lane];
            #pragma unroll
            for (int o = 16; o; o >>= 1) s += __shfl_xor_sync(0xFFFFFFFFu, s, o);
            s *= 0.125f;                    // 1/sqrt(64)
            float mn   = fmaxf(m, s);
            float corr = __expf(m - mn);    // 0 on first step (m = -inf)
            float p    = __expf(s - mn);
            l    = l * corr + p;
            acc0 = acc0 * corr + p * Vs[j * 64 + lane];
            acc1 = acc1 * corr + p * Vs[j * 64 + 32 + lane];
            m = mn;
        }
    }
    float inv = 1.0f / l;
    O[qoff + lane]      = acc0 * inv;
    O[qoff + 32 + lane] = acc1 * inv;
}

// ---------------- launch ----------------
extern "C" void kernel_launch(void* const* d_in, const int* in_sizes, int n_in,
                              void* d_out, int out_size) {
    const float* x    = (const float*)d_in[0];
    const float* ln1g = (const float*)d_in[1];
    const float* ln1b = (const float*)d_in[2];
    const float* Wq   = (const float*)d_in[3];
    const float* bq   = (const float*)d_in[4];
    const float* Wk   = (const float*)d_in[5];
    const float* bk   = (const float*)d_in[6];
    const float* Wv   = (const float*)d_in[7];
    const float* bv   = (const float*)d_in[8];
    const float* Wo   = (const float*)d_in[9];
    const float* bo   = (const float*)d_in[10];
    const float* ln2g = (const float*)d_in[11];
    const float* ln2b = (const float*)d_in[12];
    const float* W1   = (const float*)d_in[13];
    const float* b1   = (const float*)d_in[14];
    const float* W2   = (const float*)d_in[15];
    const float* b2   = (const float*)d_in[16];
    float* out = (float*)d_out;

    float *h, *q, *k, *v, *att, *x1, *ffn;
    cudaGetSymbolAddress((void**)&h,   g_h);
    cudaGetSymbolAddress((void**)&q,   g_q);
    cudaGetSymbolAddress((void**)&k,   g_k);
    cudaGetSymbolAddress((void**)&v,   g_v);
    cudaGetSymbolAddress((void**)&att, g_att);
    cudaGetSymbolAddress((void**)&x1,  g_x1);
    cudaGetSymbolAddress((void**)&ffn, g_ffn);

    dim3 gP(DMODEL / 128, N_TOK / 128);   // proj GEMMs: (8, 32)
    dim3 gF(DFF / 128,    N_TOK / 128);   // FFN GEMM1:  (32, 32)

    // --- attention sublayer ---
    ln_kernel<<<N_TOK, 256>>>(x, ln1g, ln1b, h);
    sgemm_kernel<0, 0><<<gP, 256>>>(h, Wq, bq, nullptr, q, DMODEL, DMODEL);
    sgemm_kernel<0, 0><<<gP, 256>>>(h, Wk, bk, nullptr, k, DMODEL, DMODEL);
    sgemm_kernel<0, 0><<<gP, 256>>>(h, Wv, bv, nullptr, v, DMODEL, DMODEL);
    attn_kernel<<<dim3(SEQ / 8, NHEAD, BATCH), 256>>>(q, k, v, att);
    sgemm_kernel<0, 1><<<gP, 256>>>(att, Wo, bo, x, x1, DMODEL, DMODEL);

    // --- FFN sublayer ---
    ln_kernel<<<N_TOK, 256>>>(x1, ln2g, ln2b, h);
    sgemm_kernel<1, 0><<<gF, 256>>>(h, W1, b1, nullptr, ffn, DMODEL, DFF);
    sgemm_kernel<0, 1><<<gP, 256>>>(ffn, W2, b2, x1, out, DFF, DMODEL);
}

// round 2
// speedup vs baseline: 1.6398x; 1.6398x over previous
#include <cuda_runtime.h>
#include <math.h>

#define N_TOK   4096     // B * S
#define DMODEL  1024
#define DFF     4096
#define NHEAD   16
#define DK      64
#define SEQ     2048
#define BATCH   2

// ---------------- scratch (static device globals; no allocation) ----------------
__device__ float g_h  [N_TOK * DMODEL];
__device__ float g_q  [N_TOK * DMODEL];
__device__ float g_k  [N_TOK * DMODEL];
__device__ float g_v  [N_TOK * DMODEL];
__device__ float g_att[N_TOK * DMODEL];
__device__ float g_x1 [N_TOK * DMODEL];
__device__ float g_ffn[N_TOK * DFF];

// ---------------- LayerNorm ----------------
__global__ void __launch_bounds__(256) ln_kernel(const float* __restrict__ x,
                                                 const float* __restrict__ gamma,
                                                 const float* __restrict__ beta,
                                                 float* __restrict__ out) {
    int row = blockIdx.x;
    int t = threadIdx.x;
    const float4 v = reinterpret_cast<const float4*>(x + (size_t)row * DMODEL)[t];
    float s  = v.x + v.y + v.z + v.w;
    float sq = v.x * v.x + v.y * v.y + v.z * v.z + v.w * v.w;
    #pragma unroll
    for (int o = 16; o; o >>= 1) {
        s  += __shfl_xor_sync(0xFFFFFFFFu, s,  o);
        sq += __shfl_xor_sync(0xFFFFFFFFu, sq, o);
    }
    __shared__ float ss[8], ssq[8];
    __shared__ float s_mean, s_rstd;
    int wid = t >> 5, lane = t & 31;
    if (lane == 0) { ss[wid] = s; ssq[wid] = sq; }
    __syncthreads();
    if (t == 0) {
        float ts = 0.f, tq = 0.f;
        #pragma unroll
        for (int i = 0; i < 8; i++) { ts += ss[i]; tq += ssq[i]; }
        float mean = ts * (1.0f / DMODEL);
        float var  = tq * (1.0f / DMODEL) - mean * mean;
        s_mean = mean;
        s_rstd = rsqrtf(var + 1e-5f);
    }
    __syncthreads();
    float mean = s_mean, rstd = s_rstd;
    float4 g4 = reinterpret_cast<const float4*>(gamma)[t];
    float4 b4 = reinterpret_cast<const float4*>(beta)[t];
    float4 o4;
    o4.x = (v.x - mean) * rstd * g4.x + b4.x;
    o4.y = (v.y - mean) * rstd * g4.y + b4.y;
    o4.z = (v.z - mean) * rstd * g4.z + b4.z;
    o4.w = (v.w - mean) * rstd * g4.w + b4.w;
    reinterpret_cast<float4*>(out + (size_t)row * DMODEL)[t] = o4;
}

// ---------------- SGEMM: double-buffered 128x128x8, 256 thr, 8x8/thread ----------------
template<int GELU, int RES>
__global__ void __launch_bounds__(256) sgemm_kernel(const float* __restrict__ A,
                                                    const float* __restrict__ W,
                                                    const float* __restrict__ bias,
                                                    const float* __restrict__ res,
                                                    float* __restrict__ C,
                                                    int K, int M) {
    __shared__ float As[2][8][128];
    __shared__ float Bs[2][8][128];
    int t  = threadIdx.x;
    int n0 = blockIdx.y * 128;
    int m0 = blockIdx.x * 128;

    int ar = t >> 1, ac = (t & 1) * 4;
    int br = t >> 5, bc = (t & 31) * 4;
    const float* Aptr = A + (size_t)(n0 + ar) * K + ac;
    const float* Wptr = W + (size_t)br * M + m0 + bc;

    int ty = (t >> 4) * 8;
    int tx = (t & 15) * 8;

    float acc[8][8];
    #pragma unroll
    for (int i = 0; i < 8; i++)
        #pragma unroll
        for (int j = 0; j < 8; j++) acc[i][j] = 0.f;

    // prologue: tile 0 -> buf 0
    {
        float4 a4 = *reinterpret_cast<const float4*>(Aptr);
        float4 b4 = *reinterpret_cast<const float4*>(Wptr);
        As[0][ac + 0][ar] = a4.x; As[0][ac + 1][ar] = a4.y;
        As[0][ac + 2][ar] = a4.z; As[0][ac + 3][ar] = a4.w;
        *reinterpret_cast<float4*>(&Bs[0][br][bc]) = b4;
    }
    __syncthreads();

    int nk = K >> 3;
    for (int kt = 1; kt < nk; kt++) {
        int cur = (kt - 1) & 1, nxt = kt & 1;
        float4 na = *reinterpret_cast<const float4*>(Aptr + kt * 8);
        float4 nb = *reinterpret_cast<const float4*>(Wptr + (size_t)kt * 8 * M);
        #pragma unroll
        for (int k = 0; k < 8; k++) {
            float a[8], b[8];
            *reinterpret_cast<float4*>(&a[0]) = *reinterpret_cast<float4*>(&As[cur][k][ty]);
            *reinterpret_cast<float4*>(&a[4]) = *reinterpret_cast<float4*>(&As[cur][k][ty + 4]);
            *reinterpret_cast<float4*>(&b[0]) = *reinterpret_cast<float4*>(&Bs[cur][k][tx]);
            *reinterpret_cast<float4*>(&b[4]) = *reinterpret_cast<float4*>(&Bs[cur][k][tx + 4]);
            #pragma unroll
            for (int i = 0; i < 8; i++)
                #pragma unroll
                for (int j = 0; j < 8; j++)
                    acc[i][j] = fmaf(a[i], b[j], acc[i][j]);
        }
        As[nxt][ac + 0][ar] = na.x; As[nxt][ac + 1][ar] = na.y;
        As[nxt][ac + 2][ar] = na.z; As[nxt][ac + 3][ar] = na.w;
        *reinterpret_cast<float4*>(&Bs[nxt][br][bc]) = nb;
        __syncthreads();
    }
    {
        int cur = (nk - 1) & 1;
        #pragma unroll
        for (int k = 0; k < 8; k++) {
            float a[8], b[8];
            *reinterpret_cast<float4*>(&a[0]) = *reinterpret_cast<float4*>(&As[cur][k][ty]);
            *reinterpret_cast<float4*>(&a[4]) = *reinterpret_cast<float4*>(&As[cur][k][ty + 4]);
            *reinterpret_cast<float4*>(&b[0]) = *reinterpret_cast<float4*>(&Bs[cur][k][tx]);
            *reinterpret_cast<float4*>(&b[4]) = *reinterpret_cast<float4*>(&Bs[cur][k][tx + 4]);
            #pragma unroll
            for (int i = 0; i < 8; i++)
                #pragma unroll
                for (int j = 0; j < 8; j++)
                    acc[i][j] = fmaf(a[i], b[j], acc[i][j]);
        }
    }

    float bb[8];
    #pragma unroll
    for (int j = 0; j < 8; j++) bb[j] = bias[m0 + tx + j];

    #pragma unroll
    for (int i = 0; i < 8; i++) {
        size_t off = (size_t)(n0 + ty + i) * M + m0 + tx;
        float o[8];
        #pragma unroll
        for (int j = 0; j < 8; j++) {
            float c = acc[i][j] + bb[j];
            if (GELU) c = c * normcdff(c);
            o[j] = c;
        }
        if (RES) {
            float4 r0 = *reinterpret_cast<const float4*>(res + off);
            float4 r1 = *reinterpret_cast<const float4*>(res + off + 4);
            o[0] += r0.x; o[1] += r0.y; o[2] += r0.z; o[3] += r0.w;
            o[4] += r1.x; o[5] += r1.y; o[6] += r1.z; o[7] += r1.w;
        }
        *reinterpret_cast<float4*>(C + off)     = make_float4(o[0], o[1], o[2], o[3]);
        *reinterpret_cast<float4*>(C + off + 4) = make_float4(o[4], o[5], o[6], o[7]);
    }
}

// ---------------- GEMM-style causal flash attention ----------------
// Block: 128 queries (one (b,h)), key tiles of 64. 256 threads = 16x16.
// Thread fragment: 8q x 4k scores, 8q x 4d output.
// smem: Qs[d][q] 32KB, Ks[d][k] 16KB, Vs[k][d] 17KB, Ps[k][q swizzled] 32KB.
#define ATT_SMEM ((64 * 128 + 64 * 64 + 64 * 68 + 64 * 128) * 4)

__global__ void __launch_bounds__(256, 2) attn_kernel(const float* __restrict__ Q,
                                                      const float* __restrict__ K,
                                                      const float* __restrict__ V,
                                                      float* __restrict__ O) {
    extern __shared__ float sm[];
    float* Qs = sm;                  // [64][128]  (d-major)
    float* Ks = Qs + 64 * 128;       // [64][64]   (d-major)
    float* Vs = Ks + 64 * 64;        // [64][68]   (k-major, padded)
    float* Ps = Vs + 64 * 68;        // [64][128]  (k-major, 16B-unit XOR swizzle)

    int bh = blockIdx.y;
    int b = bh >> 4, h = bh & 15;
    int qt = (SEQ / 128 - 1) - blockIdx.x;   // heavy q-tiles launch first
    int qb = qt * 128;
    int t = threadIdx.x;
    int tx = t & 15, ty = t >> 4;

    // ---- load Q tile, transposed to Qs[d][q] ----
    {
        int r = t >> 1, d0 = (t & 1) * 32;
        const float* src = Q + ((size_t)(b * SEQ + qb + r) * NHEAD + h) * DK + d0;
        #pragma unroll
        for (int i = 0; i < 8; i++) {
            float4 v4 = *reinterpret_cast<const float4*>(src + i * 4);
            int d = d0 + i * 4;
            Qs[(d + 0) * 128 + r] = v4.x;
            Qs[(d + 1) * 128 + r] = v4.y;
            Qs[(d + 2) * 128 + r] = v4.z;
            Qs[(d + 3) * 128 + r] = v4.w;
        }
    }

    float m[8], l[8], acc[8][4];
    #pragma unroll
    for (int i = 0; i < 8; i++) {
        m[i] = -INFINITY; l[i] = 0.f;
        #pragma unroll
        for (int j = 0; j < 4; j++) acc[i][j] = 0.f;
    }

    int ntiles = 2 * qt + 2;
    for (int kt = 0; kt < ntiles; kt++) {
        int k0 = kt * 64;
        __syncthreads();
        // ---- load K (transposed) and V tiles ----
        {
            int r = t >> 2, d0 = (t & 3) * 16;
            const float* kp = K + ((size_t)(b * SEQ + k0 + r) * NHEAD + h) * DK + d0;
            const float* vp = V + ((size_t)(b * SEQ + k0 + r) * NHEAD + h) * DK + d0;
            #pragma unroll
            for (int i = 0; i < 4; i++) {
                float4 kk = *reinterpret_cast<const float4*>(kp + i * 4);
                int d = d0 + i * 4;
                Ks[(d + 0) * 64 + r] = kk.x;
                Ks[(d + 1) * 64 + r] = kk.y;
                Ks[(d + 2) * 64 + r] = kk.z;
                Ks[(d + 3) * 64 + r] = kk.w;
                float4 vv = *reinterpret_cast<const float4*>(vp + i * 4);
                *reinterpret_cast<float4*>(&Vs[r * 68 + d]) = vv;
            }
        }
        __syncthreads();

        // ---- S = Q K^T  (8q x 4k per thread, k-dim = 64 head dims) ----
        float s[8][4];
        #pragma unroll
        for (int i = 0; i < 8; i++)
            #pragma unroll
            for (int j = 0; j < 4; j++) s[i][j] = 0.f;
        #pragma unroll 8
        for (int d = 0; d < 64; d++) {
            float a[8], bf[4];
            *reinterpret_cast<float4*>(&a[0]) = *reinterpret_cast<float4*>(&Qs[d * 128 + ty * 8]);
            *reinterpret_cast<float4*>(&a[4]) = *reinterpret_cast<float4*>(&Qs[d * 128 + ty * 8 + 4]);
            *reinterpret_cast<float4*>(&bf[0]) = *reinterpret_cast<float4*>(&Ks[d * 64 + tx * 4]);
            #pragma unroll
            for (int i = 0; i < 8; i++)
                #pragma unroll
                for (int j = 0; j < 4; j++)
                    s[i][j] = fmaf(a[i], bf[j], s[i][j]);
        }

        // ---- causal mask on the two diagonal tiles ----
        if (kt >= 2 * qt) {
            #pragma unroll
            for (int i = 0; i < 8; i++) {
                int qg = qb + ty * 8 + i;
                #pragma unroll
                for (int j = 0; j < 4; j++) {
                    int kg = k0 + tx * 4 + j;
                    if (kg > qg) s[i][j] = -INFINITY;
                }
            }
        }

        // ---- online softmax update (row reduce over 16 tx lanes) ----
        #pragma unroll
        for (int i = 0; i < 8; i++) {
            float mx = fmaxf(fmaxf(s[i][0], s[i][1]), fmaxf(s[i][2], s[i][3])) * 0.125f;
            #pragma unroll
            for (int o = 8; o; o >>= 1) mx = fmaxf(mx, __shfl_xor_sync(0xFFFFFFFFu, mx, o));
            float mn = fmaxf(m[i], mx);
            float corr = __expf(m[i] - mn);
            m[i] = mn;
            float rs = 0.f;
            #pragma unroll
            for (int j = 0; j < 4; j++) {
                float p = __expf(s[i][j] * 0.125f - mn);
                s[i][j] = p;           // reuse s as p
                rs += p;
            }
            #pragma unroll
            for (int o = 8; o; o >>= 1) rs += __shfl_xor_sync(0xFFFFFFFFu, rs, o);
            l[i] = l[i] * corr + rs;
            #pragma unroll
            for (int j = 0; j < 4; j++) acc[i][j] *= corr;
        }

        // ---- store P to smem, k-major, XOR-swizzled 16B units ----
        #pragma unroll
        for (int j = 0; j < 4; j++) {
            int k = tx * 4 + j;
            int xr = (k >> 2) & 15;           // == tx
            #pragma unroll
            for (int qs = 0; qs < 2; qs++) {
                int u = (ty * 2 + qs) ^ xr;
                float4 v4 = make_float4(s[qs * 4 + 0][j], s[qs * 4 + 1][j],
                                        s[qs * 4 + 2][j], s[qs * 4 + 3][j]);
                *reinterpret_cast<float4*>(&Ps[k * 128 + u * 4]) = v4;
            }
        }
        __syncthreads();

        // ---- O += P V  (8q x 4d per thread, k-dim = 64 keys) ----
        #pragma unroll 8
        for (int k = 0; k < 64; k++) {
            float a[8], bv[4];
            int xr = (k >> 2) & 15;
            *reinterpret_cast<float4*>(&a[0]) =
                *reinterpret_cast<float4*>(&Ps[k * 128 + (((ty * 2 + 0) ^ xr) * 4)]);
            *reinterpret_cast<float4*>(&a[4]) =
                *reinterpret_cast<float4*>(&Ps[k * 128 + (((ty * 2 + 1) ^ xr) * 4)]);
            *reinterpret_cast<float4*>(&bv[0]) = *reinterpret_cast<float4*>(&Vs[k * 68 + tx * 4]);
            #pragma unroll
            for (int i = 0; i < 8; i++)
                #pragma unroll
                for (int j = 0; j < 4; j++)
                    acc[i][j] = fmaf(a[i], bv[j], acc[i][j]);
        }
    }

    // ---- epilogue ----
    #pragma unroll
    for (int i = 0; i < 8; i++) {
        float inv = 1.0f / l[i];
        float4 o4 = make_float4(acc[i][0] * inv, acc[i][1] * inv,
                                acc[i][2] * inv, acc[i][3] * inv);
        float* dst = O + ((size_t)(b * SEQ + qb + ty * 8 + i) * NHEAD + h) * DK + tx * 4;
        *reinterpret_cast<float4*>(dst) = o4;
    }
}

// ---------------- launch ----------------
extern "C" void kernel_launch(void* const* d_in, const int* in_sizes, int n_in,
                              void* d_out, int out_size) {
    const float* x    = (const float*)d_in[0];
    const float* ln1g = (const float*)d_in[1];
    const float* ln1b = (const float*)d_in[2];
    const float* Wq   = (const float*)d_in[3];
    const float* bq   = (const float*)d_in[4];
    const float* Wk   = (const float*)d_in[5];
    const float* bk   = (const float*)d_in[6];
    const float* Wv   = (const float*)d_in[7];
    const float* bv   = (const float*)d_in[8];
    const float* Wo   = (const float*)d_in[9];
    const float* bo   = (const float*)d_in[10];
    const float* ln2g = (const float*)d_in[11];
    const float* ln2b = (const float*)d_in[12];
    const float* W1   = (const float*)d_in[13];
    const float* b1   = (const float*)d_in[14];
    const float* W2   = (const float*)d_in[15];
    const float* b2   = (const float*)d_in[16];
    float* out = (float*)d_out;

    float *h, *q, *k, *v, *att, *x1, *ffn;
    cudaGetSymbolAddress((void**)&h,   g_h);
    cudaGetSymbolAddress((void**)&q,   g_q);
    cudaGetSymbolAddress((void**)&k,   g_k);
    cudaGetSymbolAddress((void**)&v,   g_v);
    cudaGetSymbolAddress((void**)&att, g_att);
    cudaGetSymbolAddress((void**)&x1,  g_x1);
    cudaGetSymbolAddress((void**)&ffn, g_ffn);

    static int attn_attr_set = 0;
    if (!attn_attr_set) {
        cudaFuncSetAttribute(attn_kernel, cudaFuncAttributeMaxDynamicSharedMemorySize, ATT_SMEM);
        attn_attr_set = 1;
    }

    dim3 gP(DMODEL / 128, N_TOK / 128);
    dim3 gF(DFF / 128,    N_TOK / 128);

    // --- attention sublayer ---
    ln_kernel<<<N_TOK, 256>>>(x, ln1g, ln1b, h);
    sgemm_kernel<0, 0><<<gP, 256>>>(h, Wq, bq, nullptr, q, DMODEL, DMODEL);
    sgemm_kernel<0, 0><<<gP, 256>>>(h, Wk, bk, nullptr, k, DMODEL, DMODEL);
    sgemm_kernel<0, 0><<<gP, 256>>>(h, Wv, bv, nullptr, v, DMODEL, DMODEL);
    attn_kernel<<<dim3(SEQ / 128, NHEAD * BATCH), 256, ATT_SMEM>>>(q, k, v, att);
    sgemm_kernel<0, 1><<<gP, 256>>>(att, Wo, bo, x, x1, DMODEL, DMODEL);

    // --- FFN sublayer ---
    ln_kernel<<<N_TOK, 256>>>(x1, ln2g, ln2b, h);
    sgemm_kernel<1, 0><<<gF, 256>>>(h, W1, b1, nullptr, ffn, DMODEL, DFF);
    sgemm_kernel<0, 1><<<gP, 256>>>(ffn, W2, b2, x1, out, DFF, DMODEL);
}

// round 4
// speedup vs baseline: 3.1659x; 1.9307x over previous
#include <cuda_runtime.h>
#include <cuda_bf16.h>
#include <math.h>
#include <stdint.h>

#define N_TOK   4096     // B * S
#define DMODEL  1024
#define DFF     4096
#define NHEAD   16
#define DK      64
#define SEQ     2048
#define BATCH   2

// ---------------- scratch (static device globals; no allocation) ----------------
__device__ float g_h  [N_TOK * DMODEL];
__device__ float g_q  [N_TOK * DMODEL];
__device__ float g_k  [N_TOK * DMODEL];
__device__ float g_v  [N_TOK * DMODEL];
__device__ float g_att[N_TOK * DMODEL];
__device__ float g_x1 [N_TOK * DMODEL];
__device__ float g_ffn[N_TOK * DFF];

// split-precision weight planes, transposed to [outfeat][K]
#define WQO 0
#define WKO (1u << 20)
#define WVO (2u << 20)
#define WOO (3u << 20)
#define W1O (4u << 20)
#define W2O (8u << 20)
__device__ __nv_bfloat16 g_wh[12u << 20];
__device__ __nv_bfloat16 g_wl[12u << 20];
__device__ __nv_bfloat16 g_ah[(size_t)N_TOK * DFF];
__device__ __nv_bfloat16 g_al[(size_t)N_TOK * DFF];

// ---------------- helpers ----------------
__device__ __forceinline__ uint32_t smem_u32(const void* p) {
    uint32_t a;
    asm("{ .reg .u64 t; cvta.to.shared.u64 t, %1; cvt.u32.u64 %0, t; }" : "=r"(a) : "l"(p));
    return a;
}
__device__ __forceinline__ void cp16(uint32_t s, const void* g) {
    asm volatile("cp.async.cg.shared.global [%0], [%1], 16;" :: "r"(s), "l"(g));
}
__device__ __forceinline__ void cp_commit() {
    asm volatile("cp.async.commit_group;");
}
__device__ __forceinline__ void cp_wait1() {
    asm volatile("cp.async.wait_group 1;");
}
__device__ __forceinline__ void ldsm4(uint32_t& r0, uint32_t& r1, uint32_t& r2, uint32_t& r3,
                                      uint32_t addr) {
    asm volatile("ldmatrix.sync.aligned.m8n8.x4.shared.b16 {%0,%1,%2,%3}, [%4];"
                 : "=r"(r0), "=r"(r1), "=r"(r2), "=r"(r3) : "r"(addr));
}
__device__ __forceinline__ void mma_bf16(float* c, const uint32_t* a, uint32_t b0, uint32_t b1) {
    asm volatile("mma.sync.aligned.m16n8k16.row.col.f32.bf16.bf16.f32 "
                 "{%0,%1,%2,%3}, {%4,%5,%6,%7}, {%8,%9}, {%0,%1,%2,%3};"
                 : "+f"(c[0]), "+f"(c[1]), "+f"(c[2]), "+f"(c[3])
                 : "r"(a[0]), "r"(a[1]), "r"(a[2]), "r"(a[3]), "r"(b0), "r"(b1));
}

// ---------------- LayerNorm ----------------
__global__ void __launch_bounds__(256) ln_kernel(const float* __restrict__ x,
                                                 const float* __restrict__ gamma,
                                                 const float* __restrict__ beta,
                                                 float* __restrict__ out) {
    int row = blockIdx.x;
    int t = threadIdx.x;
    const float4 v = reinterpret_cast<const float4*>(x + (size_t)row * DMODEL)[t];
    float s  = v.x + v.y + v.z + v.w;
    float sq = v.x * v.x + v.y * v.y + v.z * v.z + v.w * v.w;
    #pragma unroll
    for (int o = 16; o; o >>= 1) {
        s  += __shfl_xor_sync(0xFFFFFFFFu, s,  o);
        sq += __shfl_xor_sync(0xFFFFFFFFu, sq, o);
    }
    __shared__ float ss[8], ssq[8];
    __shared__ float s_mean, s_rstd;
    int wid = t >> 5, lane = t & 31;
    if (lane == 0) { ss[wid] = s; ssq[wid] = sq; }
    __syncthreads();
    if (t == 0) {
        float ts = 0.f, tq = 0.f;
        #pragma unroll
        for (int i = 0; i < 8; i++) { ts += ss[i]; tq += ssq[i]; }
        float mean = ts * (1.0f / DMODEL);
        float var  = tq * (1.0f / DMODEL) - mean * mean;
        s_mean = mean;
        s_rstd = rsqrtf(var + 1e-5f);
    }
    __syncthreads();
    float mean = s_mean, rstd = s_rstd;
    float4 g4 = reinterpret_cast<const float4*>(gamma)[t];
    float4 b4 = reinterpret_cast<const float4*>(beta)[t];
    float4 o4;
    o4.x = (v.x - mean) * rstd * g4.x + b4.x;
    o4.y = (v.y - mean) * rstd * g4.y + b4.y;
    o4.z = (v.z - mean) * rstd * g4.z + b4.z;
    o4.w = (v.w - mean) * rstd * g4.w + b4.w;
    reinterpret_cast<float4*>(out + (size_t)row * DMODEL)[t] = o4;
}

// ---------------- activation split: fp32 -> bf16 hi/lo planes ----------------
__global__ void __launch_bounds__(256) split_kernel(const float* __restrict__ x,
                                                    __nv_bfloat16* __restrict__ hi,
                                                    __nv_bfloat16* __restrict__ lo) {
    size_t i = ((size_t)blockIdx.x * 256 + threadIdx.x) * 4;
    float4 v = *reinterpret_cast<const float4*>(x + i);
    __nv_bfloat16 h0 = __float2bfloat16(v.x), h1 = __float2bfloat16(v.y);
    __nv_bfloat16 h2 = __float2bfloat16(v.z), h3 = __float2bfloat16(v.w);
    __nv_bfloat16 l0 = __float2bfloat16(v.x - __bfloat162float(h0));
    __nv_bfloat16 l1 = __float2bfloat16(v.y - __bfloat162float(h1));
    __nv_bfloat16 l2 = __float2bfloat16(v.z - __bfloat162float(h2));
    __nv_bfloat16 l3 = __float2bfloat16(v.w - __bfloat162float(h3));
    uint2 uh, ul;
    uh.x = (uint32_t)__bfloat16_as_ushort(h0) | ((uint32_t)__bfloat16_as_ushort(h1) << 16);
    uh.y = (uint32_t)__bfloat16_as_ushort(h2) | ((uint32_t)__bfloat16_as_ushort(h3) << 16);
    ul.x = (uint32_t)__bfloat16_as_ushort(l0) | ((uint32_t)__bfloat16_as_ushort(l1) << 16);
    ul.y = (uint32_t)__bfloat16_as_ushort(l2) | ((uint32_t)__bfloat16_as_ushort(l3) << 16);
    *reinterpret_cast<uint2*>(hi + i) = uh;
    *reinterpret_cast<uint2*>(lo + i) = ul;
}

// ---------------- weight transpose + split: W[K][M] -> out[M][K] hi/lo ----------------
__global__ void __launch_bounds__(256) wsplit_kernel(const float* __restrict__ W,
                                                     __nv_bfloat16* __restrict__ hi,
                                                     __nv_bfloat16* __restrict__ lo,
                                                     int K, int M) {
    __shared__ float tile[32][33];
    int n0 = blockIdx.x * 32, k0 = blockIdx.y * 32;
    int tx = threadIdx.x & 31, ty = threadIdx.x >> 5;   // 32 x 8
    #pragma unroll
    for (int i = 0; i < 4; i++)
        tile[ty + 8 * i][tx] = W[(size_t)(k0 + ty + 8 * i) * M + n0 + tx];
    __syncthreads();
    #pragma unroll
    for (int i = 0; i < 4; i++) {
        float x = tile[tx][ty + 8 * i];
        __nv_bfloat16 h = __float2bfloat16(x);
        size_t o = (size_t)(n0 + ty + 8 * i) * K + k0 + tx;
        hi[o] = h;
        lo[o] = __float2bfloat16(x - __bfloat162float(h));
    }
}

// ---------------- mma.sync bf16x3 GEMM: C[rows][M] = A[rows][K] @ Bt[M][K]^T ----------------
// CTA tile 128x128, K-chunks of 32, double-buffered cp.async.
// smem per buffer: Ah[128][32] @0, Al @8192, Bh @16384, Bl @24576 (bf16, 64B rows,
// XOR swizzle: 16B unit c' = c ^ ((row>>1)&3)). Two buffers, 64KB total.
#define GEMM_SMEM 65536

template<int GELU, int RES>
__global__ void __launch_bounds__(256) gemm_mma(const __nv_bfloat16* __restrict__ Ahi,
                                                const __nv_bfloat16* __restrict__ Alo,
                                                const __nv_bfloat16* __restrict__ Bhi,
                                                const __nv_bfloat16* __restrict__ Blo,
                                                const float* __restrict__ bias,
                                                const float* __restrict__ res,
                                                float* __restrict__ C,
                                                int K, int M) {
    extern __shared__ char smc[];
    uint32_t sb = smem_u32(smc);
    int t = threadIdx.x, lane = t & 31, wid = t >> 5;
    int wr = wid & 3, wc = wid >> 2;              // warp tile: rows wr*32, cols wc*64
    int m0 = blockIdx.x * 128;
    size_t row0 = (size_t)blockIdx.y * 128;

    // -------- loader setup: thread t owns 16B chunks t and t+256 of each plane --------
    int r0 = t >> 2, cq = t & 3;
    int r1 = r0 + 64;
    uint32_t sO0 = (uint32_t)(r0 * 64 + ((cq ^ ((r0 >> 1) & 3)) << 4));
    uint32_t sO1 = (uint32_t)(r1 * 64 + ((cq ^ ((r1 >> 1) & 3)) << 4));
    const __nv_bfloat16* gA0h = Ahi + (row0 + r0) * (size_t)K + cq * 8;
    const __nv_bfloat16* gA1h = Ahi + (row0 + r1) * (size_t)K + cq * 8;
    const __nv_bfloat16* gA0l = Alo + (row0 + r0) * (size_t)K + cq * 8;
    const __nv_bfloat16* gA1l = Alo + (row0 + r1) * (size_t)K + cq * 8;
    const __nv_bfloat16* gB0h = Bhi + (size_t)(m0 + r0) * K + cq * 8;
    const __nv_bfloat16* gB1h = Bhi + (size_t)(m0 + r1) * K + cq * 8;
    const __nv_bfloat16* gB0l = Blo + (size_t)(m0 + r0) * K + cq * 8;
    const __nv_bfloat16* gB1l = Blo + (size_t)(m0 + r1) * K + cq * 8;

    // -------- ldmatrix lane address components --------
    int g = lane >> 3, l7 = lane & 7;
    // A tiles (mt = 0,1): row within CTA tile
    int arow0 = wr * 32 + 0 * 16 + l7 + ((g & 1) << 3);
    int arow1 = wr * 32 + 1 * 16 + l7 + ((g & 1) << 3);
    uint32_t aRO0 = (uint32_t)(arow0 * 64), aSW0 = (uint32_t)((arow0 >> 1) & 3);
    uint32_t aRO1 = (uint32_t)(arow1 * 64), aSW1 = (uint32_t)((arow1 >> 1) & 3);
    uint32_t aKH = (uint32_t)(g >> 1);     // k-halves select
    // B tiles (nh = 0..3): row = col within CTA tile
    int brow_base = wc * 64 + ((g >> 1) << 3) + l7;
    uint32_t bKH = (uint32_t)(g & 1);

    float acc[2][8][4];
    #pragma unroll
    for (int i = 0; i < 2; i++)
        #pragma unroll
        for (int j = 0; j < 8; j++)
            #pragma unroll
            for (int u = 0; u < 4; u++) acc[i][j][u] = 0.f;

    int NC = K >> 5;

    // prologue: chunk 0 -> buf 0
    {
        uint32_t bb = sb;
        cp16(bb + sO0,         gA0h); cp16(bb + sO1,         gA1h);
        cp16(bb + 8192  + sO0, gA0l); cp16(bb + 8192  + sO1, gA1l);
        cp16(bb + 16384 + sO0, gB0h); cp16(bb + 16384 + sO1, gB1h);
        cp16(bb + 24576 + sO0, gB0l); cp16(bb + 24576 + sO1, gB1l);
        cp_commit();
    }

    for (int kt = 0; kt < NC; kt++) {
        if (kt + 1 < NC) {
            uint32_t bb = sb + (uint32_t)((kt + 1) & 1) * 32768u;
            int ko = (kt + 1) * 32;
            cp16(bb + sO0,         gA0h + ko); cp16(bb + sO1,         gA1h + ko);
            cp16(bb + 8192  + sO0, gA0l + ko); cp16(bb + 8192  + sO1, gA1l + ko);
            cp16(bb + 16384 + sO0, gB0h + ko); cp16(bb + 16384 + sO1, gB1h + ko);
            cp16(bb + 24576 + sO0, gB0l + ko); cp16(bb + 24576 + sO1, gB1l + ko);
        }
        cp_commit();
        cp_wait1();
        __syncthreads();

        uint32_t bb = sb + (uint32_t)(kt & 1) * 32768u;
        #pragma unroll
        for (int ks = 0; ks < 2; ks++) {
            uint32_t ac = (uint32_t)(ks * 2) + aKH;
            uint32_t ah0[4], ah1[4], al0[4], al1[4];
            ldsm4(ah0[0], ah0[1], ah0[2], ah0[3], bb + aRO0 + (((ac ^ aSW0)) << 4));
            ldsm4(ah1[0], ah1[1], ah1[2], ah1[3], bb + aRO1 + (((ac ^ aSW1)) << 4));
            ldsm4(al0[0], al0[1], al0[2], al0[3], bb + 8192 + aRO0 + (((ac ^ aSW0)) << 4));
            ldsm4(al1[0], al1[1], al1[2], al1[3], bb + 8192 + aRO1 + (((ac ^ aSW1)) << 4));
            #pragma unroll
            for (int nh = 0; nh < 4; nh++) {
                int brow = brow_base + nh * 16;
                uint32_t bRO = (uint32_t)(brow * 64), bSW = (uint32_t)((brow >> 1) & 3);
                uint32_t bc = (uint32_t)(ks * 2) + bKH;
                uint32_t boff = bRO + ((bc ^ bSW) << 4);
                uint32_t bh[4], bl[4];
                ldsm4(bh[0], bh[1], bh[2], bh[3], bb + 16384 + boff);
                ldsm4(bl[0], bl[1], bl[2], bl[3], bb + 24576 + boff);
                #pragma unroll
                for (int s = 0; s < 2; s++) {
                    float* c0 = acc[0][nh * 2 + s];
                    float* c1 = acc[1][nh * 2 + s];
                    mma_bf16(c0, ah0, bh[s * 2], bh[s * 2 + 1]);
                    mma_bf16(c0, ah0, bl[s * 2], bl[s * 2 + 1]);
                    mma_bf16(c0, al0, bh[s * 2], bh[s * 2 + 1]);
                    mma_bf16(c1, ah1, bh[s * 2], bh[s * 2 + 1]);
                    mma_bf16(c1, ah1, bl[s * 2], bl[s * 2 + 1]);
                    mma_bf16(c1, al1, bh[s * 2], bh[s * 2 + 1]);
                }
            }
        }
        __syncthreads();
    }

    // -------- epilogue --------
    #pragma unroll
    for (int mt = 0; mt < 2; mt++) {
        size_t rbase = row0 + wr * 32 + mt * 16 + (lane >> 2);
        #pragma unroll
        for (int nt = 0; nt < 8; nt++) {
            int col = m0 + wc * 64 + nt * 8 + (lane & 3) * 2;
            float b0 = bias[col], b1 = bias[col + 1];
            #pragma unroll
            for (int half = 0; half < 2; half++) {
                size_t row = rbase + half * 8;
                float v0 = acc[mt][nt][half * 2 + 0] + b0;
                float v1 = acc[mt][nt][half * 2 + 1] + b1;
                if (GELU) { v0 = v0 * normcdff(v0); v1 = v1 * normcdff(v1); }
                if (RES) {
                    float2 r2 = *reinterpret_cast<const float2*>(res + row * M + col);
                    v0 += r2.x; v1 += r2.y;
                }
                *reinterpret_cast<float2*>(C + row * M + col) = make_float2(v0, v1);
            }
        }
    }
}

// ---------------- GEMM-style causal flash attention (fp32, unchanged) ----------------
#define ATT_SMEM ((64 * 128 + 64 * 64 + 64 * 68 + 64 * 128) * 4)

__global__ void __launch_bounds__(256, 2) attn_kernel(const float* __restrict__ Q,
                                                      const float* __restrict__ K,
                                                      const float* __restrict__ V,
                                                      float* __restrict__ O) {
    extern __shared__ float sm[];
    float* Qs = sm;
    float* Ks = Qs + 64 * 128;
    float* Vs = Ks + 64 * 64;
    float* Ps = Vs + 64 * 68;

    int bh = blockIdx.y;
    int b = bh >> 4, h = bh & 15;
    int qt = (SEQ / 128 - 1) - blockIdx.x;
    int qb = qt * 128;
    int t = threadIdx.x;
    int tx = t & 15, ty = t >> 4;

    {
        int r = t >> 1, d0 = (t & 1) * 32;
        const float* src = Q + ((size_t)(b * SEQ + qb + r) * NHEAD + h) * DK + d0;
        #pragma unroll
        for (int i = 0; i < 8; i++) {
            float4 v4 = *reinterpret_cast<const float4*>(src + i * 4);
            int d = d0 + i * 4;
            Qs[(d + 0) * 128 + r] = v4.x;
            Qs[(d + 1) * 128 + r] = v4.y;
            Qs[(d + 2) * 128 + r] = v4.z;
            Qs[(d + 3) * 128 + r] = v4.w;
        }
    }

    float m[8], l[8], acc[8][4];
    #pragma unroll
    for (int i = 0; i < 8; i++) {
        m[i] = -INFINITY; l[i] = 0.f;
        #pragma unroll
        for (int j = 0; j < 4; j++) acc[i][j] = 0.f;
    }

    int ntiles = 2 * qt + 2;
    for (int kt = 0; kt < ntiles; kt++) {
        int k0 = kt * 64;
        __syncthreads();
        {
            int r = t >> 2, d0 = (t & 3) * 16;
            const float* kp = K + ((size_t)(b * SEQ + k0 + r) * NHEAD + h) * DK + d0;
            const float* vp = V + ((size_t)(b * SEQ + k0 + r) * NHEAD + h) * DK + d0;
            #pragma unroll
            for (int i = 0; i < 4; i++) {
                float4 kk = *reinterpret_cast<const float4*>(kp + i * 4);
                int d = d0 + i * 4;
                Ks[(d + 0) * 64 + r] = kk.x;
                Ks[(d + 1) * 64 + r] = kk.y;
                Ks[(d + 2) * 64 + r] = kk.z;
                Ks[(d + 3) * 64 + r] = kk.w;
                float4 vv = *reinterpret_cast<const float4*>(vp + i * 4);
                *reinterpret_cast<float4*>(&Vs[r * 68 + d]) = vv;
            }
        }
        __syncthreads();

        float s[8][4];
        #pragma unroll
        for (int i = 0; i < 8; i++)
            #pragma unroll
            for (int j = 0; j < 4; j++) s[i][j] = 0.f;
        #pragma unroll 8
        for (int d = 0; d < 64; d++) {
            float a[8], bf[4];
            *reinterpret_cast<float4*>(&a[0]) = *reinterpret_cast<float4*>(&Qs[d * 128 + ty * 8]);
            *reinterpret_cast<float4*>(&a[4]) = *reinterpret_cast<float4*>(&Qs[d * 128 + ty * 8 + 4]);
            *reinterpret_cast<float4*>(&bf[0]) = *reinterpret_cast<float4*>(&Ks[d * 64 + tx * 4]);
            #pragma unroll
            for (int i = 0; i < 8; i++)
                #pragma unroll
                for (int j = 0; j < 4; j++)
                    s[i][j] = fmaf(a[i], bf[j], s[i][j]);
        }

        if (kt >= 2 * qt) {
            #pragma unroll
            for (int i = 0; i < 8; i++) {
                int qg = qb + ty * 8 + i;
                #pragma unroll
                for (int j = 0; j < 4; j++) {
                    int kg = k0 + tx * 4 + j;
                    if (kg > qg) s[i][j] = -INFINITY;
                }
            }
        }

        #pragma unroll
        for (int i = 0; i < 8; i++) {
            float mx = fmaxf(fmaxf(s[i][0], s[i][1]), fmaxf(s[i][2], s[i][3])) * 0.125f;
            #pragma unroll
            for (int o = 8; o; o >>= 1) mx = fmaxf(mx, __shfl_xor_sync(0xFFFFFFFFu, mx, o));
            float mn = fmaxf(m[i], mx);
            float corr = __expf(m[i] - mn);
            m[i] = mn;
            float rs = 0.f;
            #pragma unroll
            for (int j = 0; j < 4; j++) {
                float p = __expf(s[i][j] * 0.125f - mn);
                s[i][j] = p;
                rs += p;
            }
            #pragma unroll
            for (int o = 8; o; o >>= 1) rs += __shfl_xor_sync(0xFFFFFFFFu, rs, o);
            l[i] = l[i] * corr + rs;
            #pragma unroll
            for (int j = 0; j < 4; j++) acc[i][j] *= corr;
        }

        #pragma unroll
        for (int j = 0; j < 4; j++) {
            int k = tx * 4 + j;
            int xr2 = (k >> 2) & 15;
            #pragma unroll
            for (int qs = 0; qs < 2; qs++) {
                int u = (ty * 2 + qs) ^ xr2;
                float4 v4 = make_float4(s[qs * 4 + 0][j], s[qs * 4 + 1][j],
                                        s[qs * 4 + 2][j], s[qs * 4 + 3][j]);
                *reinterpret_cast<float4*>(&Ps[k * 128 + u * 4]) = v4;
            }
        }
        __syncthreads();

        #pragma unroll 8
        for (int k = 0; k < 64; k++) {
            float a[8], bv[4];
            int xr2 = (k >> 2) & 15;
            *reinterpret_cast<float4*>(&a[0]) =
                *reinterpret_cast<float4*>(&Ps[k * 128 + (((ty * 2 + 0) ^ xr2) * 4)]);
            *reinterpret_cast<float4*>(&a[4]) =
                *reinterpret_cast<float4*>(&Ps[k * 128 + (((ty * 2 + 1) ^ xr2) * 4)]);
            *reinterpret_cast<float4*>(&bv[0]) = *reinterpret_cast<float4*>(&Vs[k * 68 + tx * 4]);
            #pragma unroll
            for (int i = 0; i < 8; i++)
                #pragma unroll
                for (int j = 0; j < 4; j++)
                    acc[i][j] = fmaf(a[i], bv[j], acc[i][j]);
        }
    }

    #pragma unroll
    for (int i = 0; i < 8; i++) {
        float inv = 1.0f / l[i];
        float4 o4 = make_float4(acc[i][0] * inv, acc[i][1] * inv,
                                acc[i][2] * inv, acc[i][3] * inv);
        float* dst = O + ((size_t)(b * SEQ + qb + ty * 8 + i) * NHEAD + h) * DK + tx * 4;
        *reinterpret_cast<float4*>(dst) = o4;
    }
}

// ---------------- launch ----------------
extern "C" void kernel_launch(void* const* d_in, const int* in_sizes, int n_in,
                              void* d_out, int out_size) {
    const float* x    = (const float*)d_in[0];
    const float* ln1g = (const float*)d_in[1];
    const float* ln1b = (const float*)d_in[2];
    const float* Wq   = (const float*)d_in[3];
    const float* bq   = (const float*)d_in[4];
    const float* Wk   = (const float*)d_in[5];
    const float* bk   = (const float*)d_in[6];
    const float* Wv   = (const float*)d_in[7];
    const float* bv   = (const float*)d_in[8];
    const float* Wo   = (const float*)d_in[9];
    const float* bo   = (const float*)d_in[10];
    const float* ln2g = (const float*)d_in[11];
    const float* ln2b = (const float*)d_in[12];
    const float* W1   = (const float*)d_in[13];
    const float* b1   = (const float*)d_in[14];
    const float* W2   = (const float*)d_in[15];
    const float* b2   = (const float*)d_in[16];
    float* out = (float*)d_out;

    float *h, *q, *k, *v, *att, *x1, *ffn;
    __nv_bfloat16 *wh, *wl, *ah, *al;
    cudaGetSymbolAddress((void**)&h,   g_h);
    cudaGetSymbolAddress((void**)&q,   g_q);
    cudaGetSymbolAddress((void**)&k,   g_k);
    cudaGetSymbolAddress((void**)&v,   g_v);
    cudaGetSymbolAddress((void**)&att, g_att);
    cudaGetSymbolAddress((void**)&x1,  g_x1);
    cudaGetSymbolAddress((void**)&ffn, g_ffn);
    cudaGetSymbolAddress((void**)&wh,  g_wh);
    cudaGetSymbolAddress((void**)&wl,  g_wl);
    cudaGetSymbolAddress((void**)&ah,  g_ah);
    cudaGetSymbolAddress((void**)&al,  g_al);

    static int attr_set = 0;
    if (!attr_set) {
        cudaFuncSetAttribute(attn_kernel, cudaFuncAttributeMaxDynamicSharedMemorySize, ATT_SMEM);
        cudaFuncSetAttribute(gemm_mma<0, 0>, cudaFuncAttributeMaxDynamicSharedMemorySize, GEMM_SMEM);
        cudaFuncSetAttribute(gemm_mma<0, 1>, cudaFuncAttributeMaxDynamicSharedMemorySize, GEMM_SMEM);
        cudaFuncSetAttribute(gemm_mma<1, 0>, cudaFuncAttributeMaxDynamicSharedMemorySize, GEMM_SMEM);
        attr_set = 1;
    }

    dim3 wb(256);
    wsplit_kernel<<<dim3(32, 32),  wb>>>(Wq, wh + WQO, wl + WQO, DMODEL, DMODEL);
    wsplit_kernel<<<dim3(32, 32),  wb>>>(Wk, wh + WKO, wl + WKO, DMODEL, DMODEL);
    wsplit_kernel<<<dim3(32, 32),  wb>>>(Wv, wh + WVO, wl + WVO, DMODEL, DMODEL);
    wsplit_kernel<<<dim3(32, 32),  wb>>>(Wo, wh + WOO, wl + WOO, DMODEL, DMODEL);
    wsplit_kernel<<<dim3(128, 32), wb>>>(W1, wh + W1O, wl + W1O, DMODEL, DFF);
    wsplit_kernel<<<dim3(32, 128), wb>>>(W2, wh + W2O, wl + W2O, DFF, DMODEL);

    dim3 gP(8, 32), gF(32, 32);
    int nD = N_TOK * DMODEL / 1024;
    int nF = N_TOK * DFF / 1024;

    // --- attention sublayer ---
    ln_kernel<<<N_TOK, 256>>>(x, ln1g, ln1b, h);
    split_kernel<<<nD, 256>>>(h, ah, al);
    gemm_mma<0, 0><<<gP, 256, GEMM_SMEM>>>(ah, al, wh + WQO, wl + WQO, bq, nullptr, q, DMODEL, DMODEL);
    gemm_mma<0, 0><<<gP, 256, GEMM_SMEM>>>(ah, al, wh + WKO, wl + WKO, bk, nullptr, k, DMODEL, DMODEL);
    gemm_mma<0, 0><<<gP, 256, GEMM_SMEM>>>(ah, al, wh + WVO, wl + WVO, bv, nullptr, v, DMODEL, DMODEL);
    attn_kernel<<<dim3(SEQ / 128, NHEAD * BATCH), 256, ATT_SMEM>>>(q, k, v, att);
    split_kernel<<<nD, 256>>>(att, ah, al);
    gemm_mma<0, 1><<<gP, 256, GEMM_SMEM>>>(ah, al, wh + WOO, wl + WOO, bo, x, x1, DMODEL, DMODEL);

    // --- FFN sublayer ---
    ln_kernel<<<N_TOK, 256>>>(x1, ln2g, ln2b, h);
    split_kernel<<<nD, 256>>>(h, ah, al);
    gemm_mma<1, 0><<<gF, 256, GEMM_SMEM>>>(ah, al, wh + W1O, wl + W1O, b1, nullptr, ffn, DMODEL, DFF);
    split_kernel<<<nF, 256>>>(ffn, ah, al);
    gemm_mma<0, 1><<<gP, 256, GEMM_SMEM>>>(ah, al, wh + W2O, wl + W2O, b2, x1, out, DFF, DMODEL);
}

// round 5
// speedup vs baseline: 4.2547x; 1.3439x over previous
#include <cuda_runtime.h>
#include <cuda_bf16.h>
#include <math.h>
#include <stdint.h>

#define N_TOK   4096     // B * S
#define DMODEL  1024
#define DFF     4096
#define NHEAD   16
#define DK      64
#define SEQ     2048
#define BATCH   2
#define QKV_M   3072

// ---------------- scratch (static device globals; no allocation) ----------------
// weight planes, transposed to [outfeat][K]
#define WQO 0
#define WKO (1u << 20)
#define WVO (2u << 20)
#define WOO (3u << 20)
#define W1O (4u << 20)
#define W2O (8u << 20)
__device__ __nv_bfloat16 g_wh[12u << 20];
__device__ __nv_bfloat16 g_wl[12u << 20];

__device__ __nv_bfloat16 g_hh [N_TOK * DMODEL];   // LN output hi/lo
__device__ __nv_bfloat16 g_hl [N_TOK * DMODEL];
__device__ __nv_bfloat16 g_qkvh[(size_t)N_TOK * QKV_M];
__device__ __nv_bfloat16 g_qkvl[(size_t)N_TOK * QKV_M];
__device__ __nv_bfloat16 g_oh [N_TOK * DMODEL];   // attention out hi/lo
__device__ __nv_bfloat16 g_ol [N_TOK * DMODEL];
__device__ __nv_bfloat16 g_fh [(size_t)N_TOK * DFF];
__device__ __nv_bfloat16 g_fl [(size_t)N_TOK * DFF];
__device__ float g_x1[N_TOK * DMODEL];
__device__ float g_b3[QKV_M];

// ---------------- helpers ----------------
__device__ __forceinline__ uint32_t smem_u32(const void* p) {
    uint32_t a;
    asm("{ .reg .u64 t; cvta.to.shared.u64 t, %1; cvt.u32.u64 %0, t; }" : "=r"(a) : "l"(p));
    return a;
}
__device__ __forceinline__ void cp16(uint32_t s, const void* g) {
    asm volatile("cp.async.cg.shared.global [%0], [%1], 16;" :: "r"(s), "l"(g));
}
__device__ __forceinline__ void cp_commit() { asm volatile("cp.async.commit_group;"); }
__device__ __forceinline__ void cp_wait1()  { asm volatile("cp.async.wait_group 1;"); }
__device__ __forceinline__ void cp_wait0()  { asm volatile("cp.async.wait_group 0;"); }
__device__ __forceinline__ void ldsm4(uint32_t* r, uint32_t addr) {
    asm volatile("ldmatrix.sync.aligned.m8n8.x4.shared.b16 {%0,%1,%2,%3}, [%4];"
                 : "=r"(r[0]), "=r"(r[1]), "=r"(r[2]), "=r"(r[3]) : "r"(addr));
}
__device__ __forceinline__ void ldsm4t(uint32_t* r, uint32_t addr) {
    asm volatile("ldmatrix.sync.aligned.m8n8.x4.trans.shared.b16 {%0,%1,%2,%3}, [%4];"
                 : "=r"(r[0]), "=r"(r[1]), "=r"(r[2]), "=r"(r[3]) : "r"(addr));
}
__device__ __forceinline__ void mma_bf16(float* c, const uint32_t* a, uint32_t b0, uint32_t b1) {
    asm volatile("mma.sync.aligned.m16n8k16.row.col.f32.bf16.bf16.f32 "
                 "{%0,%1,%2,%3}, {%4,%5,%6,%7}, {%8,%9}, {%0,%1,%2,%3};"
                 : "+f"(c[0]), "+f"(c[1]), "+f"(c[2]), "+f"(c[3])
                 : "r"(a[0]), "r"(a[1]), "r"(a[2]), "r"(a[3]), "r"(b0), "r"(b1));
}
__device__ __forceinline__ uint32_t cvt2(float lo, float hi) {
    uint32_t r;
    asm("cvt.rn.bf16x2.f32 %0, %1, %2;" : "=r"(r) : "f"(hi), "f"(lo));
    return r;
}
// 2^y on the FMA pipe (y <= 0; clamped below -125). rel err ~1e-7.
__device__ __forceinline__ float fexp2(float y) {
    y = fmaxf(y, -125.f);
    float r = y + 12582912.f;
    float f = y - (r - 12582912.f);
    int n = __float_as_int(r) - 0x4B400000;
    float p = 0.0013333558f;
    p = fmaf(p, f, 0.0096181291f);
    p = fmaf(p, f, 0.055504109f);
    p = fmaf(p, f, 0.24022651f);
    p = fmaf(p, f, 0.69314718f);
    p = fmaf(p, f, 1.0f);
    return p * __int_as_float((n + 127) << 23);
}

// ---------------- LayerNorm (fused bf16 hi/lo split output) ----------------
__global__ void __launch_bounds__(256) ln_kernel(const float* __restrict__ x,
                                                 const float* __restrict__ gamma,
                                                 const float* __restrict__ beta,
                                                 __nv_bfloat16* __restrict__ ohi,
                                                 __nv_bfloat16* __restrict__ olo) {
    int row = blockIdx.x;
    int t = threadIdx.x;
    const float4 v = reinterpret_cast<const float4*>(x + (size_t)row * DMODEL)[t];
    float s  = v.x + v.y + v.z + v.w;
    float sq = v.x * v.x + v.y * v.y + v.z * v.z + v.w * v.w;
    #pragma unroll
    for (int o = 16; o; o >>= 1) {
        s  += __shfl_xor_sync(0xFFFFFFFFu, s,  o);
        sq += __shfl_xor_sync(0xFFFFFFFFu, sq, o);
    }
    __shared__ float ss[8], ssq[8];
    __shared__ float s_mean, s_rstd;
    int wid = t >> 5, lane = t & 31;
    if (lane == 0) { ss[wid] = s; ssq[wid] = sq; }
    __syncthreads();
    if (t == 0) {
        float ts = 0.f, tq = 0.f;
        #pragma unroll
        for (int i = 0; i < 8; i++) { ts += ss[i]; tq += ssq[i]; }
        float mean = ts * (1.0f / DMODEL);
        float var  = tq * (1.0f / DMODEL) - mean * mean;
        s_mean = mean;
        s_rstd = rsqrtf(var + 1e-5f);
    }
    __syncthreads();
    float mean = s_mean, rstd = s_rstd;
    float4 g4 = reinterpret_cast<const float4*>(gamma)[t];
    float4 b4 = reinterpret_cast<const float4*>(beta)[t];
    float o0 = (v.x - mean) * rstd * g4.x + b4.x;
    float o1 = (v.y - mean) * rstd * g4.y + b4.y;
    float o2 = (v.z - mean) * rstd * g4.z + b4.z;
    float o3 = (v.w - mean) * rstd * g4.w + b4.w;
    uint32_t h0 = cvt2(o0, o1), h1 = cvt2(o2, o3);
    float r0 = o0 - __uint_as_float(h0 << 16);
    float r1 = o1 - __uint_as_float(h0 & 0xFFFF0000u);
    float r2 = o2 - __uint_as_float(h1 << 16);
    float r3 = o3 - __uint_as_float(h1 & 0xFFFF0000u);
    uint32_t l0 = cvt2(r0, r1), l1 = cvt2(r2, r3);
    size_t idx = (size_t)row * DMODEL + t * 4;
    *reinterpret_cast<uint2*>(ohi + idx) = make_uint2(h0, h1);
    *reinterpret_cast<uint2*>(olo + idx) = make_uint2(l0, l1);
}

// ---------------- weight transpose + split: W[K][M] -> out[M][K] hi/lo ----------------
__global__ void __launch_bounds__(256) wsplit_kernel(const float* __restrict__ W,
                                                     __nv_bfloat16* __restrict__ hi,
                                                     __nv_bfloat16* __restrict__ lo,
                                                     int K, int M) {
    __shared__ float tile[32][33];
    int n0 = blockIdx.x * 32, k0 = blockIdx.y * 32;
    int tx = threadIdx.x & 31, ty = threadIdx.x >> 5;
    #pragma unroll
    for (int i = 0; i < 4; i++)
        tile[ty + 8 * i][tx] = W[(size_t)(k0 + ty + 8 * i) * M + n0 + tx];
    __syncthreads();
    #pragma unroll
    for (int i = 0; i < 4; i++) {
        float x = tile[tx][ty + 8 * i];
        __nv_bfloat16 h = __float2bfloat16(x);
        size_t o = (size_t)(n0 + ty + 8 * i) * K + k0 + tx;
        hi[o] = h;
        lo[o] = __float2bfloat16(x - __bfloat162float(h));
    }
}

__global__ void biascat_kernel(const float* bq, const float* bk, const float* bv, float* out) {
    int i = blockIdx.x * 256 + threadIdx.x;
    float v = (i < 1024) ? bq[i] : (i < 2048) ? bk[i - 1024] : bv[i - 2048];
    out[i] = v;
}

// ---------------- mma.sync bf16x3 GEMM ----------------
#define GEMM_SMEM 65536

template<int GELU, int RES, int SPLIT>
__global__ void __launch_bounds__(256) gemm_mma(const __nv_bfloat16* __restrict__ Ahi,
                                                const __nv_bfloat16* __restrict__ Alo,
                                                const __nv_bfloat16* __restrict__ Bhi,
                                                const __nv_bfloat16* __restrict__ Blo,
                                                const float* __restrict__ bias,
                                                const float* __restrict__ res,
                                                float* __restrict__ C,
                                                __nv_bfloat16* __restrict__ Chi,
                                                __nv_bfloat16* __restrict__ Clo,
                                                int K, int M) {
    extern __shared__ char smc[];
    uint32_t sb = smem_u32(smc);
    int t = threadIdx.x, lane = t & 31, wid = t >> 5;
    int wr = wid & 3, wc = wid >> 2;
    int m0 = blockIdx.x * 128;
    size_t row0 = (size_t)blockIdx.y * 128;

    int r0 = t >> 2, cq = t & 3;
    int r1 = r0 + 64;
    uint32_t sO0 = (uint32_t)(r0 * 64 + ((cq ^ ((r0 >> 1) & 3)) << 4));
    uint32_t sO1 = (uint32_t)(r1 * 64 + ((cq ^ ((r1 >> 1) & 3)) << 4));
    const __nv_bfloat16* gA0h = Ahi + (row0 + r0) * (size_t)K + cq * 8;
    const __nv_bfloat16* gA1h = Ahi + (row0 + r1) * (size_t)K + cq * 8;
    const __nv_bfloat16* gA0l = Alo + (row0 + r0) * (size_t)K + cq * 8;
    const __nv_bfloat16* gA1l = Alo + (row0 + r1) * (size_t)K + cq * 8;
    const __nv_bfloat16* gB0h = Bhi + (size_t)(m0 + r0) * K + cq * 8;
    const __nv_bfloat16* gB1h = Bhi + (size_t)(m0 + r1) * K + cq * 8;
    const __nv_bfloat16* gB0l = Blo + (size_t)(m0 + r0) * K + cq * 8;
    const __nv_bfloat16* gB1l = Blo + (size_t)(m0 + r1) * K + cq * 8;

    int g = lane >> 3, l7 = lane & 7;
    int arow0 = wr * 32 + l7 + ((g & 1) << 3);
    int arow1 = arow0 + 16;
    uint32_t aRO0 = (uint32_t)(arow0 * 64), aSW0 = (uint32_t)((arow0 >> 1) & 3);
    uint32_t aRO1 = (uint32_t)(arow1 * 64), aSW1 = (uint32_t)((arow1 >> 1) & 3);
    uint32_t aKH = (uint32_t)(g >> 1);
    int brow_base = wc * 64 + ((g >> 1) << 3) + l7;
    uint32_t bKH = (uint32_t)(g & 1);

    float acc[2][8][4];
    #pragma unroll
    for (int i = 0; i < 2; i++)
        #pragma unroll
        for (int j = 0; j < 8; j++)
            #pragma unroll
            for (int u = 0; u < 4; u++) acc[i][j][u] = 0.f;

    int NC = K >> 5;
    {
        uint32_t bb = sb;
        cp16(bb + sO0,         gA0h); cp16(bb + sO1,         gA1h);
        cp16(bb + 8192  + sO0, gA0l); cp16(bb + 8192  + sO1, gA1l);
        cp16(bb + 16384 + sO0, gB0h); cp16(bb + 16384 + sO1, gB1h);
        cp16(bb + 24576 + sO0, gB0l); cp16(bb + 24576 + sO1, gB1l);
        cp_commit();
    }

    for (int kt = 0; kt < NC; kt++) {
        if (kt + 1 < NC) {
            uint32_t bb = sb + (uint32_t)((kt + 1) & 1) * 32768u;
            int ko = (kt + 1) * 32;
            cp16(bb + sO0,         gA0h + ko); cp16(bb + sO1,         gA1h + ko);
            cp16(bb + 8192  + sO0, gA0l + ko); cp16(bb + 8192  + sO1, gA1l + ko);
            cp16(bb + 16384 + sO0, gB0h + ko); cp16(bb + 16384 + sO1, gB1h + ko);
            cp16(bb + 24576 + sO0, gB0l + ko); cp16(bb + 24576 + sO1, gB1l + ko);
        }
        cp_commit();
        cp_wait1();
        __syncthreads();

        uint32_t bb = sb + (uint32_t)(kt & 1) * 32768u;
        #pragma unroll
        for (int ks = 0; ks < 2; ks++) {
            uint32_t ac = (uint32_t)(ks * 2) + aKH;
            uint32_t ah0[4], ah1[4], al0[4], al1[4];
            ldsm4(ah0, bb + aRO0 + ((ac ^ aSW0) << 4));
            ldsm4(ah1, bb + aRO1 + ((ac ^ aSW1) << 4));
            ldsm4(al0, bb + 8192 + aRO0 + ((ac ^ aSW0) << 4));
            ldsm4(al1, bb + 8192 + aRO1 + ((ac ^ aSW1) << 4));
            #pragma unroll
            for (int nh = 0; nh < 4; nh++) {
                int brow = brow_base + nh * 16;
                uint32_t bRO = (uint32_t)(brow * 64), bSW = (uint32_t)((brow >> 1) & 3);
                uint32_t bc = (uint32_t)(ks * 2) + bKH;
                uint32_t boff = bRO + ((bc ^ bSW) << 4);
                uint32_t bh[4], bl[4];
                ldsm4(bh, bb + 16384 + boff);
                ldsm4(bl, bb + 24576 + boff);
                #pragma unroll
                for (int s = 0; s < 2; s++) {
                    float* c0 = acc[0][nh * 2 + s];
                    float* c1 = acc[1][nh * 2 + s];
                    mma_bf16(c0, ah0, bh[s * 2], bh[s * 2 + 1]);
                    mma_bf16(c0, ah0, bl[s * 2], bl[s * 2 + 1]);
                    mma_bf16(c0, al0, bh[s * 2], bh[s * 2 + 1]);
                    mma_bf16(c1, ah1, bh[s * 2], bh[s * 2 + 1]);
                    mma_bf16(c1, ah1, bl[s * 2], bl[s * 2 + 1]);
                    mma_bf16(c1, al1, bh[s * 2], bh[s * 2 + 1]);
                }
            }
        }
        __syncthreads();
    }

    #pragma unroll
    for (int mt = 0; mt < 2; mt++) {
        size_t rbase = row0 + wr * 32 + mt * 16 + (lane >> 2);
        #pragma unroll
        for (int nt = 0; nt < 8; nt++) {
            int col = m0 + wc * 64 + nt * 8 + (lane & 3) * 2;
            float b0 = bias[col], b1 = bias[col + 1];
            #pragma unroll
            for (int half = 0; half < 2; half++) {
                size_t row = rbase + half * 8;
                float v0 = acc[mt][nt][half * 2 + 0] + b0;
                float v1 = acc[mt][nt][half * 2 + 1] + b1;
                if (GELU) { v0 = v0 * normcdff(v0); v1 = v1 * normcdff(v1); }
                if (RES) {
                    float2 r2 = *reinterpret_cast<const float2*>(res + row * M + col);
                    v0 += r2.x; v1 += r2.y;
                }
                if (SPLIT) {
                    uint32_t hp = cvt2(v0, v1);
                    float h0 = __uint_as_float(hp << 16);
                    float h1 = __uint_as_float(hp & 0xFFFF0000u);
                    uint32_t lp = cvt2(v0 - h0, v1 - h1);
                    *reinterpret_cast<uint32_t*>(Chi + row * M + col) = hp;
                    *reinterpret_cast<uint32_t*>(Clo + row * M + col) = lp;
                } else {
                    *reinterpret_cast<float2*>(C + row * M + col) = make_float2(v0, v1);
                }
            }
        }
    }
}

// ---------------- mma.sync causal flash attention ----------------
// CTA: 128 queries of one (b,h); 8 warps x 16 q-rows. Key tiles of 64.
// smem: Qh/Ql [128][64] bf16 (32KB) + 2 x (Kh,Kl,Vh,Vl [64][64]) (64KB) = 96KB.
// rows are 128B (8 x 16B units), swizzle: unit' = unit ^ (row & 7).
#define ATT_SMEM 98304
#define SCALE_L2E 0.18033688f   // 0.125 * log2(e)

__global__ void __launch_bounds__(256) attn_mma(const __nv_bfloat16* __restrict__ qkvh,
                                                const __nv_bfloat16* __restrict__ qkvl,
                                                __nv_bfloat16* __restrict__ ohi,
                                                __nv_bfloat16* __restrict__ olo) {
    extern __shared__ char smc[];
    uint32_t sb = smem_u32(smc);
    int t = threadIdx.x, lane = t & 31, w = t >> 5;
    int g = lane >> 3, l7 = lane & 7;
    int bh = blockIdx.y;
    int b = bh >> 4, h = bh & 15;
    int qt = (SEQ / 128 - 1) - blockIdx.x;
    int qb = qt * 128;
    size_t tok0 = (size_t)(b * SEQ + qb);

    // ---- prologue loads: Q (2048 chunks) + KV tile 0 (2048 chunks) ----
    {
        #pragma unroll
        for (int i = 0; i < 8; i++) {
            int c = t + i * 256;
            int plane = c >> 10, rem = c & 1023;
            int row = rem >> 3, u = rem & 7;
            uint32_t so = (uint32_t)(plane * 16384 + row * 128 + ((u ^ (row & 7)) << 4));
            const __nv_bfloat16* gp = (plane ? qkvl : qkvh)
                + (tok0 + row) * QKV_M + h * 64 + u * 8;
            cp16(sb + so, gp);
        }
        size_t ktok = (size_t)(b * SEQ);
        #pragma unroll
        for (int i = 0; i < 8; i++) {
            int c = t + i * 256;
            int plane = c >> 9, rem = c & 511;
            int row = rem >> 3, u = rem & 7;
            uint32_t so = (uint32_t)(32768 + plane * 8192 + row * 128 + ((u ^ (row & 7)) << 4));
            const __nv_bfloat16* gp = ((plane & 1) ? qkvl : qkvh)
                + (ktok + row) * QKV_M + 1024 + (plane >> 1) * 1024 + h * 64 + u * 8;
            cp16(sb + so, gp);
        }
        cp_commit();
    }

    uint32_t qah[4][4], qal[4][4];
    float m0 = -1e30f, m1 = -1e30f, l0 = 0.f, l1 = 0.f;
    float o[8][4];
    #pragma unroll
    for (int j = 0; j < 8; j++)
        #pragma unroll
        for (int u = 0; u < 4; u++) o[j][u] = 0.f;

    int q0g = qb + w * 16 + (lane >> 2);
    int q1g = q0g + 8;

    int ntiles = 2 * qt + 2;
    for (int kt = 0; kt < ntiles; kt++) {
        int k0 = kt * 64;
        // issue next tile
        if (kt + 1 < ntiles) {
            uint32_t bufb = 32768u + (uint32_t)((kt + 1) & 1) * 32768u;
            size_t ktok = (size_t)(b * SEQ + (kt + 1) * 64);
            #pragma unroll
            for (int i = 0; i < 8; i++) {
                int c = t + i * 256;
                int plane = c >> 9, rem = c & 511;
                int row = rem >> 3, u = rem & 7;
                uint32_t so = bufb + (uint32_t)(plane * 8192 + row * 128 + ((u ^ (row & 7)) << 4));
                const __nv_bfloat16* gp = ((plane & 1) ? qkvl : qkvh)
                    + (ktok + row) * QKV_M + 1024 + (plane >> 1) * 1024 + h * 64 + u * 8;
                cp16(sb + so, gp);
            }
            cp_commit();
            cp_wait1();
        } else {
            cp_wait0();
        }
        __syncthreads();

        // load Q A-fragments once
        if (kt == 0) {
            int arow = w * 16 + (lane & 15);
            uint32_t aro = (uint32_t)(arow * 128);
            uint32_t asw = (uint32_t)(arow & 7);
            #pragma unroll
            for (int ks = 0; ks < 4; ks++) {
                uint32_t u = (uint32_t)(ks * 2) + (uint32_t)(lane >> 4);
                uint32_t off = aro + ((u ^ asw) << 4);
                ldsm4(qah[ks], sb + off);
                ldsm4(qal[ks], sb + 16384 + off);
            }
        }

        uint32_t kvb = sb + 32768u + (uint32_t)(kt & 1) * 32768u;

        // ---- S = Q K^T ----
        float s[8][4];
        #pragma unroll
        for (int j = 0; j < 8; j++)
            #pragma unroll
            for (int u = 0; u < 4; u++) s[j][u] = 0.f;

        #pragma unroll
        for (int nh = 0; nh < 4; nh++) {
            int brow = nh * 16 + ((g >> 1) << 3) + l7;
            uint32_t bro = (uint32_t)(brow * 128);
            uint32_t bsw = (uint32_t)(brow & 7);
            #pragma unroll
            for (int ks = 0; ks < 4; ks++) {
                uint32_t u = (uint32_t)(ks * 2) + (uint32_t)(g & 1);
                uint32_t off = bro + ((u ^ bsw) << 4);
                uint32_t bhf[4], blf[4];
                ldsm4(bhf, kvb + off);
                ldsm4(blf, kvb + 8192 + off);
                float* c0 = s[nh * 2];
                float* c1 = s[nh * 2 + 1];
                mma_bf16(c0, qah[ks], bhf[0], bhf[1]);
                mma_bf16(c0, qal[ks], bhf[0], bhf[1]);
                mma_bf16(c0, qah[ks], blf[0], blf[1]);
                mma_bf16(c1, qah[ks], bhf[2], bhf[3]);
                mma_bf16(c1, qal[ks], bhf[2], bhf[3]);
                mma_bf16(c1, qah[ks], blf[2], blf[3]);
            }
        }

        // ---- scale to log2 domain, causal mask, row max ----
        bool diag = (kt >= 2 * qt);
        float mx0 = -1e30f, mx1 = -1e30f;
        #pragma unroll
        for (int j = 0; j < 8; j++) {
            int kb = k0 + j * 8 + ((lane & 3) << 1);
            float y0 = s[j][0] * SCALE_L2E;
            float y1 = s[j][1] * SCALE_L2E;
            float y2 = s[j][2] * SCALE_L2E;
            float y3 = s[j][3] * SCALE_L2E;
            if (diag) {
                if (kb     > q0g) y0 = -1e30f;
                if (kb + 1 > q0g) y1 = -1e30f;
                if (kb     > q1g) y2 = -1e30f;
                if (kb + 1 > q1g) y3 = -1e30f;
            }
            s[j][0] = y0; s[j][1] = y1; s[j][2] = y2; s[j][3] = y3;
            mx0 = fmaxf(mx0, fmaxf(y0, y1));
            mx1 = fmaxf(mx1, fmaxf(y2, y3));
        }
        mx0 = fmaxf(mx0, __shfl_xor_sync(0xFFFFFFFFu, mx0, 1));
        mx0 = fmaxf(mx0, __shfl_xor_sync(0xFFFFFFFFu, mx0, 2));
        mx1 = fmaxf(mx1, __shfl_xor_sync(0xFFFFFFFFu, mx1, 1));
        mx1 = fmaxf(mx1, __shfl_xor_sync(0xFFFFFFFFu, mx1, 2));

        float m0n = fmaxf(m0, mx0), m1n = fmaxf(m1, mx1);
        float corr0 = fexp2(m0 - m0n), corr1 = fexp2(m1 - m1n);
        m0 = m0n; m1 = m1n;

        // ---- p = 2^(y - m), row sums ----
        float rs0 = 0.f, rs1 = 0.f;
        #pragma unroll
        for (int j = 0; j < 8; j++) {
            float p0 = fexp2(s[j][0] - m0);
            float p1 = fexp2(s[j][1] - m0);
            float p2 = fexp2(s[j][2] - m1);
            float p3 = fexp2(s[j][3] - m1);
            s[j][0] = p0; s[j][1] = p1; s[j][2] = p2; s[j][3] = p3;
            rs0 += p0 + p1; rs1 += p2 + p3;
        }
        rs0 += __shfl_xor_sync(0xFFFFFFFFu, rs0, 1);
        rs0 += __shfl_xor_sync(0xFFFFFFFFu, rs0, 2);
        rs1 += __shfl_xor_sync(0xFFFFFFFFu, rs1, 1);
        rs1 += __shfl_xor_sync(0xFFFFFFFFu, rs1, 2);
        l0 = l0 * corr0 + rs0;
        l1 = l1 * corr1 + rs1;
        #pragma unroll
        for (int j = 0; j < 8; j++) {
            o[j][0] *= corr0; o[j][1] *= corr0;
            o[j][2] *= corr1; o[j][3] *= corr1;
        }

        // ---- O += P V ----
        #pragma unroll
        for (int ks2 = 0; ks2 < 4; ks2++) {
            int j0 = ks2 * 2, j1 = j0 + 1;
            uint32_t aPh[4], aPl[4];
            aPh[0] = cvt2(s[j0][0], s[j0][1]);
            aPh[1] = cvt2(s[j0][2], s[j0][3]);
            aPh[2] = cvt2(s[j1][0], s[j1][1]);
            aPh[3] = cvt2(s[j1][2], s[j1][3]);
            aPl[0] = cvt2(s[j0][0] - __uint_as_float(aPh[0] << 16),
                          s[j0][1] - __uint_as_float(aPh[0] & 0xFFFF0000u));
            aPl[1] = cvt2(s[j0][2] - __uint_as_float(aPh[1] << 16),
                          s[j0][3] - __uint_as_float(aPh[1] & 0xFFFF0000u));
            aPl[2] = cvt2(s[j1][0] - __uint_as_float(aPh[2] << 16),
                          s[j1][1] - __uint_as_float(aPh[2] & 0xFFFF0000u));
            aPl[3] = cvt2(s[j1][2] - __uint_as_float(aPh[3] << 16),
                          s[j1][3] - __uint_as_float(aPh[3] & 0xFFFF0000u));

            int vrow = ks2 * 16 + ((g & 1) << 3) + l7;
            uint32_t vro = (uint32_t)(vrow * 128);
            uint32_t vsw = (uint32_t)(vrow & 7);
            #pragma unroll
            for (int dh = 0; dh < 4; dh++) {
                uint32_t u = (uint32_t)(dh * 2) + (uint32_t)(g >> 1);
                uint32_t off = vro + ((u ^ vsw) << 4);
                uint32_t vhf[4], vlf[4];
                ldsm4t(vhf, kvb + 16384 + off);
                ldsm4t(vlf, kvb + 24576 + off);
                float* c0 = o[dh * 2];
                float* c1 = o[dh * 2 + 1];
                mma_bf16(c0, aPh, vhf[0], vhf[1]);
                mma_bf16(c0, aPl, vhf[0], vhf[1]);
                mma_bf16(c0, aPh, vlf[0], vlf[1]);
                mma_bf16(c1, aPh, vhf[2], vhf[3]);
                mma_bf16(c1, aPl, vhf[2], vhf[3]);
                mma_bf16(c1, aPh, vlf[2], vlf[3]);
            }
        }
        __syncthreads();
    }

    // ---- epilogue: normalize, split to hi/lo bf16 planes ----
    float inv0 = 1.0f / l0, inv1 = 1.0f / l1;
    size_t r0o = ((size_t)(b * SEQ) + q0g) * DMODEL + h * 64;
    size_t r1o = ((size_t)(b * SEQ) + q1g) * DMODEL + h * 64;
    #pragma unroll
    for (int j = 0; j < 8; j++) {
        int col = j * 8 + (lane & 3) * 2;
        float v0 = o[j][0] * inv0, v1 = o[j][1] * inv0;
        float v2 = o[j][2] * inv1, v3 = o[j][3] * inv1;
        uint32_t hp0 = cvt2(v0, v1);
        uint32_t lp0 = cvt2(v0 - __uint_as_float(hp0 << 16),
                            v1 - __uint_as_float(hp0 & 0xFFFF0000u));
        uint32_t hp1 = cvt2(v2, v3);
        uint32_t lp1 = cvt2(v2 - __uint_as_float(hp1 << 16),
                            v3 - __uint_as_float(hp1 & 0xFFFF0000u));
        *reinterpret_cast<uint32_t*>(ohi + r0o + col) = hp0;
        *reinterpret_cast<uint32_t*>(olo + r0o + col) = lp0;
        *reinterpret_cast<uint32_t*>(ohi + r1o + col) = hp1;
        *reinterpret_cast<uint32_t*>(olo + r1o + col) = lp1;
    }
}

// ---------------- launch ----------------
extern "C" void kernel_launch(void* const* d_in, const int* in_sizes, int n_in,
                              void* d_out, int out_size) {
    const float* x    = (const float*)d_in[0];
    const float* ln1g = (const float*)d_in[1];
    const float* ln1b = (const float*)d_in[2];
    const float* Wq   = (const float*)d_in[3];
    const float* bq   = (const float*)d_in[4];
    const float* Wk   = (const float*)d_in[5];
    const float* bk   = (const float*)d_in[6];
    const float* Wv   = (const float*)d_in[7];
    const float* bv   = (const float*)d_in[8];
    const float* Wo   = (const float*)d_in[9];
    const float* bo   = (const float*)d_in[10];
    const float* ln2g = (const float*)d_in[11];
    const float* ln2b = (const float*)d_in[12];
    const float* W1   = (const float*)d_in[13];
    const float* b1   = (const float*)d_in[14];
    const float* W2   = (const float*)d_in[15];
    const float* b2   = (const float*)d_in[16];
    float* out = (float*)d_out;

    __nv_bfloat16 *wh, *wl, *hh, *hl, *qkvh, *qkvl, *oh, *ol, *fh, *fl;
    float *x1, *b3;
    cudaGetSymbolAddress((void**)&wh,   g_wh);
    cudaGetSymbolAddress((void**)&wl,   g_wl);
    cudaGetSymbolAddress((void**)&hh,   g_hh);
    cudaGetSymbolAddress((void**)&hl,   g_hl);
    cudaGetSymbolAddress((void**)&qkvh, g_qkvh);
    cudaGetSymbolAddress((void**)&qkvl, g_qkvl);
    cudaGetSymbolAddress((void**)&oh,   g_oh);
    cudaGetSymbolAddress((void**)&ol,   g_ol);
    cudaGetSymbolAddress((void**)&fh,   g_fh);
    cudaGetSymbolAddress((void**)&fl,   g_fl);
    cudaGetSymbolAddress((void**)&x1,   g_x1);
    cudaGetSymbolAddress((void**)&b3,   g_b3);

    static int attr_set = 0;
    if (!attr_set) {
        cudaFuncSetAttribute(attn_mma, cudaFuncAttributeMaxDynamicSharedMemorySize, ATT_SMEM);
        cudaFuncSetAttribute(gemm_mma<0, 0, 1>, cudaFuncAttributeMaxDynamicSharedMemorySize, GEMM_SMEM);
        cudaFuncSetAttribute(gemm_mma<0, 1, 0>, cudaFuncAttributeMaxDynamicSharedMemorySize, GEMM_SMEM);
        cudaFuncSetAttribute(gemm_mma<1, 0, 1>, cudaFuncAttributeMaxDynamicSharedMemorySize, GEMM_SMEM);
        attr_set = 1;
    }

    dim3 wb(256);
    wsplit_kernel<<<dim3(32, 32),  wb>>>(Wq, wh + WQO, wl + WQO, DMODEL, DMODEL);
    wsplit_kernel<<<dim3(32, 32),  wb>>>(Wk, wh + WKO, wl + WKO, DMODEL, DMODEL);
    wsplit_kernel<<<dim3(32, 32),  wb>>>(Wv, wh + WVO, wl + WVO, DMODEL, DMODEL);
    wsplit_kernel<<<dim3(32, 32),  wb>>>(Wo, wh + WOO, wl + WOO, DMODEL, DMODEL);
    wsplit_kernel<<<dim3(128, 32), wb>>>(W1, wh + W1O, wl + W1O, DMODEL, DFF);
    wsplit_kernel<<<dim3(32, 128), wb>>>(W2, wh + W2O, wl + W2O, DFF, DMODEL);
    biascat_kernel<<<12, 256>>>(bq, bk, bv, b3);

    // --- attention sublayer ---
    ln_kernel<<<N_TOK, 256>>>(x, ln1g, ln1b, hh, hl);
    gemm_mma<0, 0, 1><<<dim3(QKV_M / 128, 32), 256, GEMM_SMEM>>>(
        hh, hl, wh + WQO, wl + WQO, b3, nullptr, nullptr, qkvh, qkvl, DMODEL, QKV_M);
    attn_mma<<<dim3(SEQ / 128, NHEAD * BATCH), 256, ATT_SMEM>>>(qkvh, qkvl, oh, ol);
    gemm_mma<0, 1, 0><<<dim3(8, 32), 256, GEMM_SMEM>>>(
        oh, ol, wh + WOO, wl + WOO, bo, x, x1, nullptr, nullptr, DMODEL, DMODEL);

    // --- FFN sublayer ---
    ln_kernel<<<N_TOK, 256>>>(x1, ln2g, ln2b, hh, hl);
    gemm_mma<1, 0, 1><<<dim3(32, 32), 256, GEMM_SMEM>>>(
        hh, hl, wh + W1O, wl + W1O, b1, nullptr, nullptr, fh, fl, DMODEL, DFF);
    gemm_mma<0, 1, 0><<<dim3(8, 32), 256, GEMM_SMEM>>>(
        fh, fl, wh + W2O, wl + W2O, b2, x1, out, nullptr, nullptr, DFF, DMODEL);
}

// round 6
// speedup vs baseline: 4.8515x; 1.1403x over previous
#include <cuda_runtime.h>
#include <cuda_bf16.h>
#include <math.h>
#include <stdint.h>

#define N_TOK   4096     // B * S
#define DMODEL  1024
#define DFF     4096
#define NHEAD   16
#define DK      64
#define SEQ     2048
#define BATCH   2
#define QKV_M   3072

// ---------------- scratch (static device globals; no allocation) ----------------
#define WQO 0
#define WKO (1u << 20)
#define WVO (2u << 20)
#define WOO (3u << 20)
#define W1O (4u << 20)
#define W2O (8u << 20)
__device__ __nv_bfloat16 g_wh[12u << 20];
__device__ __nv_bfloat16 g_wl[12u << 20];

__device__ __nv_bfloat16 g_hh [N_TOK * DMODEL];
__device__ __nv_bfloat16 g_hl [N_TOK * DMODEL];
__device__ __nv_bfloat16 g_qkvh[(size_t)N_TOK * QKV_M];
__device__ __nv_bfloat16 g_qkvl[(size_t)N_TOK * QKV_M];
__device__ __nv_bfloat16 g_oh [N_TOK * DMODEL];
__device__ __nv_bfloat16 g_ol [N_TOK * DMODEL];
__device__ __nv_bfloat16 g_fh [(size_t)N_TOK * DFF];
__device__ __nv_bfloat16 g_fl [(size_t)N_TOK * DFF];
__device__ float g_x1[N_TOK * DMODEL];
__device__ float g_b3[QKV_M];

// ---------------- helpers ----------------
__device__ __forceinline__ uint32_t smem_u32(const void* p) {
    uint32_t a;
    asm("{ .reg .u64 t; cvta.to.shared.u64 t, %1; cvt.u32.u64 %0, t; }" : "=r"(a) : "l"(p));
    return a;
}
__device__ __forceinline__ void cp16(uint32_t s, const void* g) {
    asm volatile("cp.async.cg.shared.global [%0], [%1], 16;" :: "r"(s), "l"(g));
}
__device__ __forceinline__ void cp_commit() { asm volatile("cp.async.commit_group;"); }
__device__ __forceinline__ void cp_waitg1() { asm volatile("cp.async.wait_group 1;"); }
__device__ __forceinline__ void cp_wait1()  { asm volatile("cp.async.wait_group 1;"); }
__device__ __forceinline__ void cp_wait0()  { asm volatile("cp.async.wait_group 0;"); }
__device__ __forceinline__ void ldsm4(uint32_t* r, uint32_t addr) {
    asm volatile("ldmatrix.sync.aligned.m8n8.x4.shared.b16 {%0,%1,%2,%3}, [%4];"
                 : "=r"(r[0]), "=r"(r[1]), "=r"(r[2]), "=r"(r[3]) : "r"(addr));
}
__device__ __forceinline__ void ldsm4t(uint32_t* r, uint32_t addr) {
    asm volatile("ldmatrix.sync.aligned.m8n8.x4.trans.shared.b16 {%0,%1,%2,%3}, [%4];"
                 : "=r"(r[0]), "=r"(r[1]), "=r"(r[2]), "=r"(r[3]) : "r"(addr));
}
__device__ __forceinline__ void mma_bf16(float* c, const uint32_t* a, uint32_t b0, uint32_t b1) {
    asm volatile("mma.sync.aligned.m16n8k16.row.col.f32.bf16.bf16.f32 "
                 "{%0,%1,%2,%3}, {%4,%5,%6,%7}, {%8,%9}, {%0,%1,%2,%3};"
                 : "+f"(c[0]), "+f"(c[1]), "+f"(c[2]), "+f"(c[3])
                 : "r"(a[0]), "r"(a[1]), "r"(a[2]), "r"(a[3]), "r"(b0), "r"(b1));
}
__device__ __forceinline__ uint32_t cvt2(float lo, float hi) {
    uint32_t r;
    asm("cvt.rn.bf16x2.f32 %0, %1, %2;" : "=r"(r) : "f"(hi), "f"(lo));
    return r;
}
// 2^y on the FMA pipe (y <= 0; clamped below -125). rel err ~1e-7.
__device__ __forceinline__ float fexp2(float y) {
    y = fmaxf(y, -125.f);
    float r = y + 12582912.f;
    float f = y - (r - 12582912.f);
    int n = __float_as_int(r) - 0x4B400000;
    float p = 0.0013333558f;
    p = fmaf(p, f, 0.0096181291f);
    p = fmaf(p, f, 0.055504109f);
    p = fmaf(p, f, 0.24022651f);
    p = fmaf(p, f, 0.69314718f);
    p = fmaf(p, f, 1.0f);
    return p * __int_as_float((n + 127) << 23);
}

// ---------------- LayerNorm (fused bf16 hi/lo split output) ----------------
__global__ void __launch_bounds__(256) ln_kernel(const float* __restrict__ x,
                                                 const float* __restrict__ gamma,
                                                 const float* __restrict__ beta,
                                                 __nv_bfloat16* __restrict__ ohi,
                                                 __nv_bfloat16* __restrict__ olo) {
    int row = blockIdx.x;
    int t = threadIdx.x;
    const float4 v = reinterpret_cast<const float4*>(x + (size_t)row * DMODEL)[t];
    float s  = v.x + v.y + v.z + v.w;
    float sq = v.x * v.x + v.y * v.y + v.z * v.z + v.w * v.w;
    #pragma unroll
    for (int o = 16; o; o >>= 1) {
        s  += __shfl_xor_sync(0xFFFFFFFFu, s,  o);
        sq += __shfl_xor_sync(0xFFFFFFFFu, sq, o);
    }
    __shared__ float ss[8], ssq[8];
    __shared__ float s_mean, s_rstd;
    int wid = t >> 5, lane = t & 31;
    if (lane == 0) { ss[wid] = s; ssq[wid] = sq; }
    __syncthreads();
    if (t == 0) {
        float ts = 0.f, tq = 0.f;
        #pragma unroll
        for (int i = 0; i < 8; i++) { ts += ss[i]; tq += ssq[i]; }
        float mean = ts * (1.0f / DMODEL);
        float var  = tq * (1.0f / DMODEL) - mean * mean;
        s_mean = mean;
        s_rstd = rsqrtf(var + 1e-5f);
    }
    __syncthreads();
    float mean = s_mean, rstd = s_rstd;
    float4 g4 = reinterpret_cast<const float4*>(gamma)[t];
    float4 b4 = reinterpret_cast<const float4*>(beta)[t];
    float o0 = (v.x - mean) * rstd * g4.x + b4.x;
    float o1 = (v.y - mean) * rstd * g4.y + b4.y;
    float o2 = (v.z - mean) * rstd * g4.z + b4.z;
    float o3 = (v.w - mean) * rstd * g4.w + b4.w;
    uint32_t h0 = cvt2(o0, o1), h1 = cvt2(o2, o3);
    float r0 = o0 - __uint_as_float(h0 << 16);
    float r1 = o1 - __uint_as_float(h0 & 0xFFFF0000u);
    float r2 = o2 - __uint_as_float(h1 << 16);
    float r3 = o3 - __uint_as_float(h1 & 0xFFFF0000u);
    uint32_t l0 = cvt2(r0, r1), l1 = cvt2(r2, r3);
    size_t idx = (size_t)row * DMODEL + t * 4;
    *reinterpret_cast<uint2*>(ohi + idx) = make_uint2(h0, h1);
    *reinterpret_cast<uint2*>(olo + idx) = make_uint2(l0, l1);
}

// ---------------- all-weights transpose + split (single launch) ----------------
// tiles 0..4095: Wq/Wk/Wv/Wo (32x32 grid each); 4096..8191: W1 (128x32); 8192..12287: W2 (32x128)
__global__ void __launch_bounds__(256) wsplit_all(const float* __restrict__ Wq,
                                                  const float* __restrict__ Wk,
                                                  const float* __restrict__ Wv,
                                                  const float* __restrict__ Wo,
                                                  const float* __restrict__ W1,
                                                  const float* __restrict__ W2,
                                                  __nv_bfloat16* __restrict__ hiB,
                                                  __nv_bfloat16* __restrict__ loB) {
    __shared__ float tile[32][33];
    int id = blockIdx.x;
    const float* W;
    int K, M, n0, k0;
    uint32_t base;
    if (id < 4096) {
        int wsel = id >> 10, local = id & 1023;
        K = M = 1024;
        n0 = (local & 31) * 32; k0 = (local >> 5) * 32;
        W = (wsel == 0) ? Wq : (wsel == 1) ? Wk : (wsel == 2) ? Wv : Wo;
        base = (uint32_t)wsel << 20;
    } else if (id < 8192) {
        int local = id - 4096;
        K = 1024; M = 4096;
        n0 = (local & 127) * 32; k0 = (local >> 7) * 32;
        W = W1; base = W1O;
    } else {
        int local = id - 8192;
        K = 4096; M = 1024;
        n0 = (local & 31) * 32; k0 = (local >> 5) * 32;
        W = W2; base = W2O;
    }
    int tx = threadIdx.x & 31, ty = threadIdx.x >> 5;
    #pragma unroll
    for (int i = 0; i < 4; i++)
        tile[ty + 8 * i][tx] = W[(size_t)(k0 + ty + 8 * i) * M + n0 + tx];
    __syncthreads();
    #pragma unroll
    for (int i = 0; i < 4; i++) {
        float x = tile[tx][ty + 8 * i];
        __nv_bfloat16 h = __float2bfloat16(x);
        size_t o = (size_t)base + (size_t)(n0 + ty + 8 * i) * K + k0 + tx;
        hiB[o] = h;
        loB[o] = __float2bfloat16(x - __bfloat162float(h));
    }
}

__global__ void biascat_kernel(const float* bq, const float* bk, const float* bv, float* out) {
    int i = blockIdx.x * 256 + threadIdx.x;
    float v = (i < 1024) ? bq[i] : (i < 2048) ? bk[i - 1024] : bv[i - 2048];
    out[i] = v;
}

// ---------------- mma.sync bf16x3 GEMM (3-stage cp.async pipeline) ----------------
#define GEMM_SMEM (3 * 32768)

template<int GELU, int RES, int SPLIT>
__global__ void __launch_bounds__(256, 2) gemm_mma(const __nv_bfloat16* __restrict__ Ahi,
                                                   const __nv_bfloat16* __restrict__ Alo,
                                                   const __nv_bfloat16* __restrict__ Bhi,
                                                   const __nv_bfloat16* __restrict__ Blo,
                                                   const float* __restrict__ bias,
                                                   const float* __restrict__ res,
                                                   float* __restrict__ C,
                                                   __nv_bfloat16* __restrict__ Chi,
                                                   __nv_bfloat16* __restrict__ Clo,
                                                   int K, int M) {
    extern __shared__ char smc[];
    uint32_t sb = smem_u32(smc);
    int t = threadIdx.x, lane = t & 31, wid = t >> 5;
    int wr = wid & 3, wc = wid >> 2;
    int m0 = blockIdx.x * 128;
    size_t row0 = (size_t)blockIdx.y * 128;

    int r0 = t >> 2, cq = t & 3;
    int r1 = r0 + 64;
    uint32_t sO0 = (uint32_t)(r0 * 64 + ((cq ^ ((r0 >> 1) & 3)) << 4));
    uint32_t sO1 = (uint32_t)(r1 * 64 + ((cq ^ ((r1 >> 1) & 3)) << 4));
    const __nv_bfloat16* gA0h = Ahi + (row0 + r0) * (size_t)K + cq * 8;
    const __nv_bfloat16* gA1h = Ahi + (row0 + r1) * (size_t)K + cq * 8;
    const __nv_bfloat16* gA0l = Alo + (row0 + r0) * (size_t)K + cq * 8;
    const __nv_bfloat16* gA1l = Alo + (row0 + r1) * (size_t)K + cq * 8;
    const __nv_bfloat16* gB0h = Bhi + (size_t)(m0 + r0) * K + cq * 8;
    const __nv_bfloat16* gB1h = Bhi + (size_t)(m0 + r1) * K + cq * 8;
    const __nv_bfloat16* gB0l = Blo + (size_t)(m0 + r0) * K + cq * 8;
    const __nv_bfloat16* gB1l = Blo + (size_t)(m0 + r1) * K + cq * 8;

    int g = lane >> 3, l7 = lane & 7;
    int arow0 = wr * 32 + l7 + ((g & 1) << 3);
    int arow1 = arow0 + 16;
    uint32_t aRO0 = (uint32_t)(arow0 * 64), aSW0 = (uint32_t)((arow0 >> 1) & 3);
    uint32_t aRO1 = (uint32_t)(arow1 * 64), aSW1 = (uint32_t)((arow1 >> 1) & 3);
    uint32_t aKH = (uint32_t)(g >> 1);
    int brow_base = wc * 64 + ((g >> 1) << 3) + l7;
    uint32_t bKH = (uint32_t)(g & 1);

    float acc[2][8][4];
    #pragma unroll
    for (int i = 0; i < 2; i++)
        #pragma unroll
        for (int j = 0; j < 8; j++)
            #pragma unroll
            for (int u = 0; u < 4; u++) acc[i][j][u] = 0.f;

    int NC = K >> 5;

    // prologue: chunks 0,1 -> stages 0,1
    #pragma unroll
    for (int pk = 0; pk < 2; pk++) {
        uint32_t bb = sb + (uint32_t)pk * 32768u;
        int ko = pk * 32;
        cp16(bb + sO0,         gA0h + ko); cp16(bb + sO1,         gA1h + ko);
        cp16(bb + 8192  + sO0, gA0l + ko); cp16(bb + 8192  + sO1, gA1l + ko);
        cp16(bb + 16384 + sO0, gB0h + ko); cp16(bb + 16384 + sO1, gB1h + ko);
        cp16(bb + 24576 + sO0, gB0l + ko); cp16(bb + 24576 + sO1, gB1l + ko);
        cp_commit();
    }

    int stage = 0, nstage = 2;   // stage of chunk kt, stage for chunk kt+2
    for (int kt = 0; kt < NC; kt++) {
        cp_waitg1();          // chunk kt complete (kt+1 may be in flight)
        __syncthreads();      // all warps done reading the stage we're about to overwrite

        if (kt + 2 < NC) {
            uint32_t bb = sb + (uint32_t)nstage * 32768u;
            int ko = (kt + 2) * 32;
            cp16(bb + sO0,         gA0h + ko); cp16(bb + sO1,         gA1h + ko);
            cp16(bb + 8192  + sO0, gA0l + ko); cp16(bb + 8192  + sO1, gA1l + ko);
            cp16(bb + 16384 + sO0, gB0h + ko); cp16(bb + 16384 + sO1, gB1h + ko);
            cp16(bb + 24576 + sO0, gB0l + ko); cp16(bb + 24576 + sO1, gB1l + ko);
        }
        cp_commit();

        uint32_t bb = sb + (uint32_t)stage * 32768u;
        #pragma unroll
        for (int ks = 0; ks < 2; ks++) {
            uint32_t ac = (uint32_t)(ks * 2) + aKH;
            uint32_t ah0[4], ah1[4], al0[4], al1[4];
            ldsm4(ah0, bb + aRO0 + ((ac ^ aSW0) << 4));
            ldsm4(ah1, bb + aRO1 + ((ac ^ aSW1) << 4));
            ldsm4(al0, bb + 8192 + aRO0 + ((ac ^ aSW0) << 4));
            ldsm4(al1, bb + 8192 + aRO1 + ((ac ^ aSW1) << 4));
            #pragma unroll
            for (int nh = 0; nh < 4; nh++) {
                int brow = brow_base + nh * 16;
                uint32_t bRO = (uint32_t)(brow * 64), bSW = (uint32_t)((brow >> 1) & 3);
                uint32_t bc = (uint32_t)(ks * 2) + bKH;
                uint32_t boff = bRO + ((bc ^ bSW) << 4);
                uint32_t bh[4], bl[4];
                ldsm4(bh, bb + 16384 + boff);
                ldsm4(bl, bb + 24576 + boff);
                #pragma unroll
                for (int s = 0; s < 2; s++) {
                    float* c0 = acc[0][nh * 2 + s];
                    float* c1 = acc[1][nh * 2 + s];
                    mma_bf16(c0, ah0, bh[s * 2], bh[s * 2 + 1]);
                    mma_bf16(c0, ah0, bl[s * 2], bl[s * 2 + 1]);
                    mma_bf16(c0, al0, bh[s * 2], bh[s * 2 + 1]);
                    mma_bf16(c1, ah1, bh[s * 2], bh[s * 2 + 1]);
                    mma_bf16(c1, ah1, bl[s * 2], bl[s * 2 + 1]);
                    mma_bf16(c1, al1, bh[s * 2], bh[s * 2 + 1]);
                }
            }
        }
        stage = (stage == 2) ? 0 : stage + 1;
        nstage = (nstage == 2) ? 0 : nstage + 1;
    }

    #pragma unroll
    for (int mt = 0; mt < 2; mt++) {
        size_t rbase = row0 + wr * 32 + mt * 16 + (lane >> 2);
        #pragma unroll
        for (int nt = 0; nt < 8; nt++) {
            int col = m0 + wc * 64 + nt * 8 + (lane & 3) * 2;
            float b0 = bias[col], b1 = bias[col + 1];
            #pragma unroll
            for (int half = 0; half < 2; half++) {
                size_t row = rbase + half * 8;
                float v0 = acc[mt][nt][half * 2 + 0] + b0;
                float v1 = acc[mt][nt][half * 2 + 1] + b1;
                if (GELU) { v0 = v0 * normcdff(v0); v1 = v1 * normcdff(v1); }
                if (RES) {
                    float2 r2 = *reinterpret_cast<const float2*>(res + row * M + col);
                    v0 += r2.x; v1 += r2.y;
                }
                if (SPLIT) {
                    uint32_t hp = cvt2(v0, v1);
                    float h0 = __uint_as_float(hp << 16);
                    float h1 = __uint_as_float(hp & 0xFFFF0000u);
                    uint32_t lp = cvt2(v0 - h0, v1 - h1);
                    *reinterpret_cast<uint32_t*>(Chi + row * M + col) = hp;
                    *reinterpret_cast<uint32_t*>(Clo + row * M + col) = lp;
                } else {
                    *reinterpret_cast<float2*>(C + row * M + col) = make_float2(v0, v1);
                }
            }
        }
    }
}

// ---------------- mma.sync causal flash attention (unchanged from R5) ----------------
#define ATT_SMEM 98304
#define SCALE_L2E 0.18033688f   // 0.125 * log2(e)

__global__ void __launch_bounds__(256) attn_mma(const __nv_bfloat16* __restrict__ qkvh,
                                                const __nv_bfloat16* __restrict__ qkvl,
                                                __nv_bfloat16* __restrict__ ohi,
                                                __nv_bfloat16* __restrict__ olo) {
    extern __shared__ char smc[];
    uint32_t sb = smem_u32(smc);
    int t = threadIdx.x, lane = t & 31, w = t >> 5;
    int g = lane >> 3, l7 = lane & 7;
    int bh = blockIdx.y;
    int b = bh >> 4, h = bh & 15;
    int qt = (SEQ / 128 - 1) - blockIdx.x;
    int qb = qt * 128;
    size_t tok0 = (size_t)(b * SEQ + qb);

    {
        #pragma unroll
        for (int i = 0; i < 8; i++) {
            int c = t + i * 256;
            int plane = c >> 10, rem = c & 1023;
            int row = rem >> 3, u = rem & 7;
            uint32_t so = (uint32_t)(plane * 16384 + row * 128 + ((u ^ (row & 7)) << 4));
            const __nv_bfloat16* gp = (plane ? qkvl : qkvh)
                + (tok0 + row) * QKV_M + h * 64 + u * 8;
            cp16(sb + so, gp);
        }
        size_t ktok = (size_t)(b * SEQ);
        #pragma unroll
        for (int i = 0; i < 8; i++) {
            int c = t + i * 256;
            int plane = c >> 9, rem = c & 511;
            int row = rem >> 3, u = rem & 7;
            uint32_t so = (uint32_t)(32768 + plane * 8192 + row * 128 + ((u ^ (row & 7)) << 4));
            const __nv_bfloat16* gp = ((plane & 1) ? qkvl : qkvh)
                + (ktok + row) * QKV_M + 1024 + (plane >> 1) * 1024 + h * 64 + u * 8;
            cp16(sb + so, gp);
        }
        cp_commit();
    }

    uint32_t qah[4][4], qal[4][4];
    float m0 = -1e30f, m1 = -1e30f, l0 = 0.f, l1 = 0.f;
    float o[8][4];
    #pragma unroll
    for (int j = 0; j < 8; j++)
        #pragma unroll
        for (int u = 0; u < 4; u++) o[j][u] = 0.f;

    int q0g = qb + w * 16 + (lane >> 2);
    int q1g = q0g + 8;

    int ntiles = 2 * qt + 2;
    for (int kt = 0; kt < ntiles; kt++) {
        int k0 = kt * 64;
        if (kt + 1 < ntiles) {
            uint32_t bufb = 32768u + (uint32_t)((kt + 1) & 1) * 32768u;
            size_t ktok = (size_t)(b * SEQ + (kt + 1) * 64);
            #pragma unroll
            for (int i = 0; i < 8; i++) {
                int c = t + i * 256;
                int plane = c >> 9, rem = c & 511;
                int row = rem >> 3, u = rem & 7;
                uint32_t so = bufb + (uint32_t)(plane * 8192 + row * 128 + ((u ^ (row & 7)) << 4));
                const __nv_bfloat16* gp = ((plane & 1) ? qkvl : qkvh)
                    + (ktok + row) * QKV_M + 1024 + (plane >> 1) * 1024 + h * 64 + u * 8;
                cp16(sb + so, gp);
            }
            cp_commit();
            cp_wait1();
        } else {
            cp_wait0();
        }
        __syncthreads();

        if (kt == 0) {
            int arow = w * 16 + (lane & 15);
            uint32_t aro = (uint32_t)(arow * 128);
            uint32_t asw = (uint32_t)(arow & 7);
            #pragma unroll
            for (int ks = 0; ks < 4; ks++) {
                uint32_t u = (uint32_t)(ks * 2) + (uint32_t)(lane >> 4);
                uint32_t off = aro + ((u ^ asw) << 4);
                ldsm4(qah[ks], sb + off);
                ldsm4(qal[ks], sb + 16384 + off);
            }
        }

        uint32_t kvb = sb + 32768u + (uint32_t)(kt & 1) * 32768u;

        float s[8][4];
        #pragma unroll
        for (int j = 0; j < 8; j++)
            #pragma unroll
            for (int u = 0; u < 4; u++) s[j][u] = 0.f;

        #pragma unroll
        for (int nh = 0; nh < 4; nh++) {
            int brow = nh * 16 + ((g >> 1) << 3) + l7;
            uint32_t bro = (uint32_t)(brow * 128);
            uint32_t bsw = (uint32_t)(brow & 7);
            #pragma unroll
            for (int ks = 0; ks < 4; ks++) {
                uint32_t u = (uint32_t)(ks * 2) + (uint32_t)(g & 1);
                uint32_t off = bro + ((u ^ bsw) << 4);
                uint32_t bhf[4], blf[4];
                ldsm4(bhf, kvb + off);
                ldsm4(blf, kvb + 8192 + off);
                float* c0 = s[nh * 2];
                float* c1 = s[nh * 2 + 1];
                mma_bf16(c0, qah[ks], bhf[0], bhf[1]);
                mma_bf16(c0, qal[ks], bhf[0], bhf[1]);
                mma_bf16(c0, qah[ks], blf[0], blf[1]);
                mma_bf16(c1, qah[ks], bhf[2], bhf[3]);
                mma_bf16(c1, qal[ks], bhf[2], bhf[3]);
                mma_bf16(c1, qah[ks], blf[2], blf[3]);
            }
        }

        bool diag = (kt >= 2 * qt);
        float mx0 = -1e30f, mx1 = -1e30f;
        #pragma unroll
        for (int j = 0; j < 8; j++) {
            int kb = k0 + j * 8 + ((lane & 3) << 1);
            float y0 = s[j][0] * SCALE_L2E;
            float y1 = s[j][1] * SCALE_L2E;
            float y2 = s[j][2] * SCALE_L2E;
            float y3 = s[j][3] * SCALE_L2E;
            if (diag) {
                if (kb     > q0g) y0 = -1e30f;
                if (kb + 1 > q0g) y1 = -1e30f;
                if (kb     > q1g) y2 = -1e30f;
                if (kb + 1 > q1g) y3 = -1e30f;
            }
            s[j][0] = y0; s[j][1] = y1; s[j][2] = y2; s[j][3] = y3;
            mx0 = fmaxf(mx0, fmaxf(y0, y1));
            mx1 = fmaxf(mx1, fmaxf(y2, y3));
        }
        mx0 = fmaxf(mx0, __shfl_xor_sync(0xFFFFFFFFu, mx0, 1));
        mx0 = fmaxf(mx0, __shfl_xor_sync(0xFFFFFFFFu, mx0, 2));
        mx1 = fmaxf(mx1, __shfl_xor_sync(0xFFFFFFFFu, mx1, 1));
        mx1 = fmaxf(mx1, __shfl_xor_sync(0xFFFFFFFFu, mx1, 2));

        float m0n = fmaxf(m0, mx0), m1n = fmaxf(m1, mx1);
        float corr0 = fexp2(m0 - m0n), corr1 = fexp2(m1 - m1n);
        m0 = m0n; m1 = m1n;

        float rs0 = 0.f, rs1 = 0.f;
        #pragma unroll
        for (int j = 0; j < 8; j++) {
            float p0 = fexp2(s[j][0] - m0);
            float p1 = fexp2(s[j][1] - m0);
            float p2 = fexp2(s[j][2] - m1);
            float p3 = fexp2(s[j][3] - m1);
            s[j][0] = p0; s[j][1] = p1; s[j][2] = p2; s[j][3] = p3;
            rs0 += p0 + p1; rs1 += p2 + p3;
        }
        rs0 += __shfl_xor_sync(0xFFFFFFFFu, rs0, 1);
        rs0 += __shfl_xor_sync(0xFFFFFFFFu, rs0, 2);
        rs1 += __shfl_xor_sync(0xFFFFFFFFu, rs1, 1);
        rs1 += __shfl_xor_sync(0xFFFFFFFFu, rs1, 2);
        l0 = l0 * corr0 + rs0;
        l1 = l1 * corr1 + rs1;
        #pragma unroll
        for (int j = 0; j < 8; j++) {
            o[j][0] *= corr0; o[j][1] *= corr0;
            o[j][2] *= corr1; o[j][3] *= corr1;
        }

        #pragma unroll
        for (int ks2 = 0; ks2 < 4; ks2++) {
            int j0 = ks2 * 2, j1 = j0 + 1;
            uint32_t aPh[4], aPl[4];
            aPh[0] = cvt2(s[j0][0], s[j0][1]);
            aPh[1] = cvt2(s[j0][2], s[j0][3]);
            aPh[2] = cvt2(s[j1][0], s[j1][1]);
            aPh[3] = cvt2(s[j1][2], s[j1][3]);
            aPl[0] = cvt2(s[j0][0] - __uint_as_float(aPh[0] << 16),
                          s[j0][1] - __uint_as_float(aPh[0] & 0xFFFF0000u));
            aPl[1] = cvt2(s[j0][2] - __uint_as_float(aPh[1] << 16),
                          s[j0][3] - __uint_as_float(aPh[1] & 0xFFFF0000u));
            aPl[2] = cvt2(s[j1][0] - __uint_as_float(aPh[2] << 16),
                          s[j1][1] - __uint_as_float(aPh[2] & 0xFFFF0000u));
            aPl[3] = cvt2(s[j1][2] - __uint_as_float(aPh[3] << 16),
                          s[j1][3] - __uint_as_float(aPh[3] & 0xFFFF0000u));

            int vrow = ks2 * 16 + ((g & 1) << 3) + l7;
            uint32_t vro = (uint32_t)(vrow * 128);
            uint32_t vsw = (uint32_t)(vrow & 7);
            #pragma unroll
            for (int dh = 0; dh < 4; dh++) {
                uint32_t u = (uint32_t)(dh * 2) + (uint32_t)(g >> 1);
                uint32_t off = vro + ((u ^ vsw) << 4);
                uint32_t vhf[4], vlf[4];
                ldsm4t(vhf, kvb + 16384 + off);
                ldsm4t(vlf, kvb + 24576 + off);
                float* c0 = o[dh * 2];
                float* c1 = o[dh * 2 + 1];
                mma_bf16(c0, aPh, vhf[0], vhf[1]);
                mma_bf16(c0, aPl, vhf[0], vhf[1]);
                mma_bf16(c0, aPh, vlf[0], vlf[1]);
                mma_bf16(c1, aPh, vhf[2], vhf[3]);
                mma_bf16(c1, aPl, vhf[2], vhf[3]);
                mma_bf16(c1, aPh, vlf[2], vlf[3]);
            }
        }
        __syncthreads();
    }

    float inv0 = 1.0f / l0, inv1 = 1.0f / l1;
    size_t r0o = ((size_t)(b * SEQ) + q0g) * DMODEL + h * 64;
    size_t r1o = ((size_t)(b * SEQ) + q1g) * DMODEL + h * 64;
    #pragma unroll
    for (int j = 0; j < 8; j++) {
        int col = j * 8 + (lane & 3) * 2;
        float v0 = o[j][0] * inv0, v1 = o[j][1] * inv0;
        float v2 = o[j][2] * inv1, v3 = o[j][3] * inv1;
        uint32_t hp0 = cvt2(v0, v1);
        uint32_t lp0 = cvt2(v0 - __uint_as_float(hp0 << 16),
                            v1 - __uint_as_float(hp0 & 0xFFFF0000u));
        uint32_t hp1 = cvt2(v2, v3);
        uint32_t lp1 = cvt2(v2 - __uint_as_float(hp1 << 16),
                            v3 - __uint_as_float(hp1 & 0xFFFF0000u));
        *reinterpret_cast<uint32_t*>(ohi + r0o + col) = hp0;
        *reinterpret_cast<uint32_t*>(olo + r0o + col) = lp0;
        *reinterpret_cast<uint32_t*>(ohi + r1o + col) = hp1;
        *reinterpret_cast<uint32_t*>(olo + r1o + col) = lp1;
    }
}

// ---------------- launch ----------------
extern "C" void kernel_launch(void* const* d_in, const int* in_sizes, int n_in,
                              void* d_out, int out_size) {
    const float* x    = (const float*)d_in[0];
    const float* ln1g = (const float*)d_in[1];
    const float* ln1b = (const float*)d_in[2];
    const float* Wq   = (const float*)d_in[3];
    const float* bq   = (const float*)d_in[4];
    const float* Wk   = (const float*)d_in[5];
    const float* bk   = (const float*)d_in[6];
    const float* Wv   = (const float*)d_in[7];
    const float* bv   = (const float*)d_in[8];
    const float* Wo   = (const float*)d_in[9];
    const float* bo   = (const float*)d_in[10];
    const float* ln2g = (const float*)d_in[11];
    const float* ln2b = (const float*)d_in[12];
    const float* W1   = (const float*)d_in[13];
    const float* b1   = (const float*)d_in[14];
    const float* W2   = (const float*)d_in[15];
    const float* b2   = (const float*)d_in[16];
    float* out = (float*)d_out;

    __nv_bfloat16 *wh, *wl, *hh, *hl, *qkvh, *qkvl, *oh, *ol, *fh, *fl;
    float *x1, *b3;
    cudaGetSymbolAddress((void**)&wh,   g_wh);
    cudaGetSymbolAddress((void**)&wl,   g_wl);
    cudaGetSymbolAddress((void**)&hh,   g_hh);
    cudaGetSymbolAddress((void**)&hl,   g_hl);
    cudaGetSymbolAddress((void**)&qkvh, g_qkvh);
    cudaGetSymbolAddress((void**)&qkvl, g_qkvl);
    cudaGetSymbolAddress((void**)&oh,   g_oh);
    cudaGetSymbolAddress((void**)&ol,   g_ol);
    cudaGetSymbolAddress((void**)&fh,   g_fh);
    cudaGetSymbolAddress((void**)&fl,   g_fl);
    cudaGetSymbolAddress((void**)&x1,   g_x1);
    cudaGetSymbolAddress((void**)&b3,   g_b3);

    static int attr_set = 0;
    if (!attr_set) {
        cudaFuncSetAttribute(attn_mma, cudaFuncAttributeMaxDynamicSharedMemorySize, ATT_SMEM);
        cudaFuncSetAttribute(gemm_mma<0, 0, 1>, cudaFuncAttributeMaxDynamicSharedMemorySize, GEMM_SMEM);
        cudaFuncSetAttribute(gemm_mma<0, 1, 0>, cudaFuncAttributeMaxDynamicSharedMemorySize, GEMM_SMEM);
        cudaFuncSetAttribute(gemm_mma<1, 0, 1>, cudaFuncAttributeMaxDynamicSharedMemorySize, GEMM_SMEM);
        attr_set = 1;
    }

    wsplit_all<<<12288, 256>>>(Wq, Wk, Wv, Wo, W1, W2, wh, wl);
    biascat_kernel<<<12, 256>>>(bq, bk, bv, b3);

    // --- attention sublayer ---
    ln_kernel<<<N_TOK, 256>>>(x, ln1g, ln1b, hh, hl);
    gemm_mma<0, 0, 1><<<dim3(QKV_M / 128, 32), 256, GEMM_SMEM>>>(
        hh, hl, wh + WQO, wl + WQO, b3, nullptr, nullptr, qkvh, qkvl, DMODEL, QKV_M);
    attn_mma<<<dim3(SEQ / 128, NHEAD * BATCH), 256, ATT_SMEM>>>(qkvh, qkvl, oh, ol);
    gemm_mma<0, 1, 0><<<dim3(8, 32), 256, GEMM_SMEM>>>(
        oh, ol, wh + WOO, wl + WOO, bo, x, x1, nullptr, nullptr, DMODEL, DMODEL);

    // --- FFN sublayer ---
    ln_kernel<<<N_TOK, 256>>>(x1, ln2g, ln2b, hh, hl);
    gemm_mma<1, 0, 1><<<dim3(32, 32), 256, GEMM_SMEM>>>(
        hh, hl, wh + W1O, wl + W1O, b1, nullptr, nullptr, fh, fl, DMODEL, DFF);
    gemm_mma<0, 1, 0><<<dim3(8, 32), 256, GEMM_SMEM>>>(
        fh, fl, wh + W2O, wl + W2O, b2, x1, out, nullptr, nullptr, DFF, DMODEL);
}

// round 7
// speedup vs baseline: 6.6182x; 1.3642x over previous
#include <cuda_runtime.h>
#include <cuda_fp16.h>
#include <math.h>
#include <stdint.h>

#define N_TOK   4096     // B * S
#define DMODEL  1024
#define DFF     4096
#define NHEAD   16
#define DK      64
#define SEQ     2048
#define BATCH   2
#define QKV_M   3072

// ---------------- scratch (static device globals; no allocation) ----------------
#define WQO 0
#define WKO (1u << 20)
#define WVO (2u << 20)
#define WOO (3u << 20)
#define W1O (4u << 20)
#define W2O (8u << 20)
__device__ __half g_w  [12u << 20];                 // weights: single fp16 plane, [outfeat][K]
__device__ __half g_hh [N_TOK * DMODEL];            // LN out hi/lo
__device__ __half g_hl [N_TOK * DMODEL];
__device__ __half g_qkvh[(size_t)N_TOK * QKV_M];
__device__ __half g_qkvl[(size_t)N_TOK * QKV_M];
__device__ __half g_oh [N_TOK * DMODEL];
__device__ __half g_ol [N_TOK * DMODEL];
__device__ __half g_fh [(size_t)N_TOK * DFF];
__device__ __half g_fl [(size_t)N_TOK * DFF];
__device__ float g_x1[N_TOK * DMODEL];
__device__ float g_b3[QKV_M];

// ---------------- helpers ----------------
__device__ __forceinline__ uint32_t smem_u32(const void* p) {
    uint32_t a;
    asm("{ .reg .u64 t; cvta.to.shared.u64 t, %1; cvt.u32.u64 %0, t; }" : "=r"(a) : "l"(p));
    return a;
}
__device__ __forceinline__ void cp16(uint32_t s, const void* g) {
    asm volatile("cp.async.cg.shared.global [%0], [%1], 16;" :: "r"(s), "l"(g));
}
__device__ __forceinline__ void cp_commit() { asm volatile("cp.async.commit_group;"); }
__device__ __forceinline__ void cp_wait2()  { asm volatile("cp.async.wait_group 2;"); }
__device__ __forceinline__ void cp_wait1()  { asm volatile("cp.async.wait_group 1;"); }
__device__ __forceinline__ void cp_wait0()  { asm volatile("cp.async.wait_group 0;"); }
__device__ __forceinline__ void ldsm4(uint32_t* r, uint32_t addr) {
    asm volatile("ldmatrix.sync.aligned.m8n8.x4.shared.b16 {%0,%1,%2,%3}, [%4];"
                 : "=r"(r[0]), "=r"(r[1]), "=r"(r[2]), "=r"(r[3]) : "r"(addr));
}
__device__ __forceinline__ void ldsm4t(uint32_t* r, uint32_t addr) {
    asm volatile("ldmatrix.sync.aligned.m8n8.x4.trans.shared.b16 {%0,%1,%2,%3}, [%4];"
                 : "=r"(r[0]), "=r"(r[1]), "=r"(r[2]), "=r"(r[3]) : "r"(addr));
}
__device__ __forceinline__ void mma_f16(float* c, const uint32_t* a, uint32_t b0, uint32_t b1) {
    asm volatile("mma.sync.aligned.m16n8k16.row.col.f32.f16.f16.f32 "
                 "{%0,%1,%2,%3}, {%4,%5,%6,%7}, {%8,%9}, {%0,%1,%2,%3};"
                 : "+f"(c[0]), "+f"(c[1]), "+f"(c[2]), "+f"(c[3])
                 : "r"(a[0]), "r"(a[1]), "r"(a[2]), "r"(a[3]), "r"(b0), "r"(b1));
}
__device__ __forceinline__ uint32_t f2h2(float a, float b) {
    __half2 h = __floats2half2_rn(a, b);
    return *reinterpret_cast<uint32_t*>(&h);
}
// 2^y on the FMA pipe (y <= 0; clamped below -125). rel err ~1e-7.
__device__ __forceinline__ float fexp2(float y) {
    y = fmaxf(y, -125.f);
    float r = y + 12582912.f;
    float f = y - (r - 12582912.f);
    int n = __float_as_int(r) - 0x4B400000;
    float p = 0.0013333558f;
    p = fmaf(p, f, 0.0096181291f);
    p = fmaf(p, f, 0.055504109f);
    p = fmaf(p, f, 0.24022651f);
    p = fmaf(p, f, 0.69314718f);
    p = fmaf(p, f, 1.0f);
    return p * __int_as_float((n + 127) << 23);
}

// ---------------- LayerNorm (fused fp16 hi/lo split output) ----------------
__global__ void __launch_bounds__(256) ln_kernel(const float* __restrict__ x,
                                                 const float* __restrict__ gamma,
                                                 const float* __restrict__ beta,
                                                 __half* __restrict__ ohi,
                                                 __half* __restrict__ olo) {
    int row = blockIdx.x;
    int t = threadIdx.x;
    const float4 v = reinterpret_cast<const float4*>(x + (size_t)row * DMODEL)[t];
    float s  = v.x + v.y + v.z + v.w;
    float sq = v.x * v.x + v.y * v.y + v.z * v.z + v.w * v.w;
    #pragma unroll
    for (int o = 16; o; o >>= 1) {
        s  += __shfl_xor_sync(0xFFFFFFFFu, s,  o);
        sq += __shfl_xor_sync(0xFFFFFFFFu, sq, o);
    }
    __shared__ float ss[8], ssq[8];
    __shared__ float s_mean, s_rstd;
    int wid = t >> 5, lane = t & 31;
    if (lane == 0) { ss[wid] = s; ssq[wid] = sq; }
    __syncthreads();
    if (t == 0) {
        float ts = 0.f, tq = 0.f;
        #pragma unroll
        for (int i = 0; i < 8; i++) { ts += ss[i]; tq += ssq[i]; }
        float mean = ts * (1.0f / DMODEL);
        float var  = tq * (1.0f / DMODEL) - mean * mean;
        s_mean = mean;
        s_rstd = rsqrtf(var + 1e-5f);
    }
    __syncthreads();
    float mean = s_mean, rstd = s_rstd;
    float4 g4 = reinterpret_cast<const float4*>(gamma)[t];
    float4 b4 = reinterpret_cast<const float4*>(beta)[t];
    float o0 = (v.x - mean) * rstd * g4.x + b4.x;
    float o1 = (v.y - mean) * rstd * g4.y + b4.y;
    float o2 = (v.z - mean) * rstd * g4.z + b4.z;
    float o3 = (v.w - mean) * rstd * g4.w + b4.w;
    __half2 h0 = __floats2half2_rn(o0, o1), h1 = __floats2half2_rn(o2, o3);
    __half2 l0 = __floats2half2_rn(o0 - __low2float(h0), o1 - __high2float(h0));
    __half2 l1 = __floats2half2_rn(o2 - __low2float(h1), o3 - __high2float(h1));
    size_t idx = (size_t)row * DMODEL + t * 4;
    *reinterpret_cast<__half2*>(ohi + idx)     = h0;
    *reinterpret_cast<__half2*>(ohi + idx + 2) = h1;
    *reinterpret_cast<__half2*>(olo + idx)     = l0;
    *reinterpret_cast<__half2*>(olo + idx + 2) = l1;
}

// ---------------- all-weights transpose + fp16 convert (single launch) ----------------
__global__ void __launch_bounds__(256) wsplit_all(const float* __restrict__ Wq,
                                                  const float* __restrict__ Wk,
                                                  const float* __restrict__ Wv,
                                                  const float* __restrict__ Wo,
                                                  const float* __restrict__ W1,
                                                  const float* __restrict__ W2,
                                                  __half* __restrict__ out) {
    __shared__ float tile[32][33];
    int id = blockIdx.x;
    const float* W;
    int K, M, n0, k0;
    uint32_t base;
    if (id < 4096) {
        int wsel = id >> 10, local = id & 1023;
        K = M = 1024;
        n0 = (local & 31) * 32; k0 = (local >> 5) * 32;
        W = (wsel == 0) ? Wq : (wsel == 1) ? Wk : (wsel == 2) ? Wv : Wo;
        base = (uint32_t)wsel << 20;
    } else if (id < 8192) {
        int local = id - 4096;
        K = 1024; M = 4096;
        n0 = (local & 127) * 32; k0 = (local >> 7) * 32;
        W = W1; base = W1O;
    } else {
        int local = id - 8192;
        K = 4096; M = 1024;
        n0 = (local & 31) * 32; k0 = (local >> 5) * 32;
        W = W2; base = W2O;
    }
    int tx = threadIdx.x & 31, ty = threadIdx.x >> 5;
    #pragma unroll
    for (int i = 0; i < 4; i++)
        tile[ty + 8 * i][tx] = W[(size_t)(k0 + ty + 8 * i) * M + n0 + tx];
    __syncthreads();
    #pragma unroll
    for (int i = 0; i < 4; i++) {
        float x = tile[tx][ty + 8 * i];
        out[(size_t)base + (size_t)(n0 + ty + 8 * i) * K + k0 + tx] = __float2half_rn(x);
    }
}

__global__ void biascat_kernel(const float* bq, const float* bk, const float* bv, float* out) {
    int i = blockIdx.x * 256 + threadIdx.x;
    float v = (i < 1024) ? bq[i] : (i < 2048) ? bk[i - 1024] : bv[i - 2048];
    out[i] = v;
}

// ---------------- mma.sync fp16x2 GEMM (A split hi/lo, B single plane) ----------------
// 4-stage cp.async pipeline. Stage = Ah(8KB) + Al(8KB) + Bh(8KB) = 24KB; 4 stages = 96KB.
#define GEMM_SMEM (4 * 24576)

template<int GELU, int RES, int SPLIT>
__global__ void __launch_bounds__(256, 2) gemm_mma(const __half* __restrict__ Ahi,
                                                   const __half* __restrict__ Alo,
                                                   const __half* __restrict__ Bh,
                                                   const float* __restrict__ bias,
                                                   const float* __restrict__ res,
                                                   float* __restrict__ C,
                                                   __half* __restrict__ Chi,
                                                   __half* __restrict__ Clo,
                                                   int K, int M) {
    extern __shared__ char smc[];
    uint32_t sb = smem_u32(smc);
    int t = threadIdx.x, lane = t & 31, wid = t >> 5;
    int wr = wid & 3, wc = wid >> 2;
    int m0 = blockIdx.x * 128;
    size_t row0 = (size_t)blockIdx.y * 128;

    int r0 = t >> 2, cq = t & 3;
    int r1 = r0 + 64;
    uint32_t sO0 = (uint32_t)(r0 * 64 + ((cq ^ ((r0 >> 1) & 3)) << 4));
    uint32_t sO1 = (uint32_t)(r1 * 64 + ((cq ^ ((r1 >> 1) & 3)) << 4));
    const __half* gA0h = Ahi + (row0 + r0) * (size_t)K + cq * 8;
    const __half* gA1h = Ahi + (row0 + r1) * (size_t)K + cq * 8;
    const __half* gA0l = Alo + (row0 + r0) * (size_t)K + cq * 8;
    const __half* gA1l = Alo + (row0 + r1) * (size_t)K + cq * 8;
    const __half* gB0  = Bh  + (size_t)(m0 + r0) * K + cq * 8;
    const __half* gB1  = Bh  + (size_t)(m0 + r1) * K + cq * 8;

    int g = lane >> 3, l7 = lane & 7;
    int arow0 = wr * 32 + l7 + ((g & 1) << 3);
    int arow1 = arow0 + 16;
    uint32_t aRO0 = (uint32_t)(arow0 * 64), aSW0 = (uint32_t)((arow0 >> 1) & 3);
    uint32_t aRO1 = (uint32_t)(arow1 * 64), aSW1 = (uint32_t)((arow1 >> 1) & 3);
    uint32_t aKH = (uint32_t)(g >> 1);
    int brow_base = wc * 64 + ((g >> 1) << 3) + l7;
    uint32_t bKH = (uint32_t)(g & 1);

    float acc[2][8][4];
    #pragma unroll
    for (int i = 0; i < 2; i++)
        #pragma unroll
        for (int j = 0; j < 8; j++)
            #pragma unroll
            for (int u = 0; u < 4; u++) acc[i][j][u] = 0.f;

    int NC = K >> 5;

    // prologue: chunks 0..2 -> stages 0..2
    #pragma unroll
    for (int pk = 0; pk < 3; pk++) {
        uint32_t bb = sb + (uint32_t)pk * 24576u;
        int ko = pk * 32;
        cp16(bb + sO0,         gA0h + ko); cp16(bb + sO1,         gA1h + ko);
        cp16(bb + 8192  + sO0, gA0l + ko); cp16(bb + 8192  + sO1, gA1l + ko);
        cp16(bb + 16384 + sO0, gB0  + ko); cp16(bb + 16384 + sO1, gB1  + ko);
        cp_commit();
    }

    for (int kt = 0; kt < NC; kt++) {
        cp_wait2();           // chunk kt complete (kt+1, kt+2 may be in flight)
        __syncthreads();

        if (kt + 3 < NC) {
            uint32_t bb = sb + (uint32_t)((kt + 3) & 3) * 24576u;
            int ko = (kt + 3) * 32;
            cp16(bb + sO0,         gA0h + ko); cp16(bb + sO1,         gA1h + ko);
            cp16(bb + 8192  + sO0, gA0l + ko); cp16(bb + 8192  + sO1, gA1l + ko);
            cp16(bb + 16384 + sO0, gB0  + ko); cp16(bb + 16384 + sO1, gB1  + ko);
        }
        cp_commit();

        uint32_t bb = sb + (uint32_t)(kt & 3) * 24576u;
        #pragma unroll
        for (int ks = 0; ks < 2; ks++) {
            uint32_t ac = (uint32_t)(ks * 2) + aKH;
            uint32_t ah0[4], ah1[4], al0[4], al1[4];
            ldsm4(ah0, bb + aRO0 + ((ac ^ aSW0) << 4));
            ldsm4(ah1, bb + aRO1 + ((ac ^ aSW1) << 4));
            ldsm4(al0, bb + 8192 + aRO0 + ((ac ^ aSW0) << 4));
            ldsm4(al1, bb + 8192 + aRO1 + ((ac ^ aSW1) << 4));
            #pragma unroll
            for (int nh = 0; nh < 4; nh++) {
                int brow = brow_base + nh * 16;
                uint32_t bRO = (uint32_t)(brow * 64), bSW = (uint32_t)((brow >> 1) & 3);
                uint32_t bc = (uint32_t)(ks * 2) + bKH;
                uint32_t boff = bRO + ((bc ^ bSW) << 4);
                uint32_t bh[4];
                ldsm4(bh, bb + 16384 + boff);
                #pragma unroll
                for (int s = 0; s < 2; s++) {
                    float* c0 = acc[0][nh * 2 + s];
                    float* c1 = acc[1][nh * 2 + s];
                    mma_f16(c0, ah0, bh[s * 2], bh[s * 2 + 1]);
                    mma_f16(c0, al0, bh[s * 2], bh[s * 2 + 1]);
                    mma_f16(c1, ah1, bh[s * 2], bh[s * 2 + 1]);
                    mma_f16(c1, al1, bh[s * 2], bh[s * 2 + 1]);
                }
            }
        }
    }

    #pragma unroll
    for (int mt = 0; mt < 2; mt++) {
        size_t rbase = row0 + wr * 32 + mt * 16 + (lane >> 2);
        #pragma unroll
        for (int nt = 0; nt < 8; nt++) {
            int col = m0 + wc * 64 + nt * 8 + (lane & 3) * 2;
            float b0 = bias[col], b1 = bias[col + 1];
            #pragma unroll
            for (int half = 0; half < 2; half++) {
                size_t row = rbase + half * 8;
                float v0 = acc[mt][nt][half * 2 + 0] + b0;
                float v1 = acc[mt][nt][half * 2 + 1] + b1;
                if (GELU) { v0 = v0 * normcdff(v0); v1 = v1 * normcdff(v1); }
                if (RES) {
                    float2 r2 = *reinterpret_cast<const float2*>(res + row * M + col);
                    v0 += r2.x; v1 += r2.y;
                }
                if (SPLIT) {
                    __half2 hp = __floats2half2_rn(v0, v1);
                    __half2 lp = __floats2half2_rn(v0 - __low2float(hp),
                                                   v1 - __high2float(hp));
                    *reinterpret_cast<__half2*>(Chi + row * M + col) = hp;
                    *reinterpret_cast<__half2*>(Clo + row * M + col) = lp;
                } else {
                    *reinterpret_cast<float2*>(C + row * M + col) = make_float2(v0, v1);
                }
            }
        }
    }
}

// ---------------- mma.sync causal flash attention (fp16x2) ----------------
// smem: Qh [128][64] @0 (16KB), Ql @16384 (16KB); KV stages @32768: 2 x (Kh 8KB + Vh 8KB).
#define ATT_SMEM 65536
#define SCALE_L2E 0.18033688f   // 0.125 * log2(e)

__global__ void __launch_bounds__(256) attn_mma(const __half* __restrict__ qkvh,
                                                const __half* __restrict__ qkvl,
                                                __half* __restrict__ ohi,
                                                __half* __restrict__ olo) {
    extern __shared__ char smc[];
    uint32_t sb = smem_u32(smc);
    int t = threadIdx.x, lane = t & 31, w = t >> 5;
    int g = lane >> 3, l7 = lane & 7;
    int bh = blockIdx.y;
    int b = bh >> 4, h = bh & 15;
    int qt = (SEQ / 128 - 1) - blockIdx.x;
    int qb = qt * 128;
    size_t tok0 = (size_t)(b * SEQ + qb);

    // prologue: Q hi/lo (2048 chunks) + KV tile 0 (1024 chunks)
    {
        #pragma unroll
        for (int i = 0; i < 8; i++) {
            int c = t + i * 256;
            int plane = c >> 10, rem = c & 1023;
            int row = rem >> 3, u = rem & 7;
            uint32_t so = (uint32_t)(plane * 16384 + row * 128 + ((u ^ (row & 7)) << 4));
            const __half* gp = (plane ? qkvl : qkvh) + (tok0 + row) * QKV_M + h * 64 + u * 8;
            cp16(sb + so, gp);
        }
        size_t ktok = (size_t)(b * SEQ);
        #pragma unroll
        for (int i = 0; i < 4; i++) {
            int c = t + i * 256;
            int plane = c >> 9, rem = c & 511;   // 0=K, 1=V
            int row = rem >> 3, u = rem & 7;
            uint32_t so = (uint32_t)(32768 + plane * 8192 + row * 128 + ((u ^ (row & 7)) << 4));
            const __half* gp = qkvh + (ktok + row) * QKV_M + 1024 + plane * 1024 + h * 64 + u * 8;
            cp16(sb + so, gp);
        }
        cp_commit();
    }

    uint32_t qah[4][4], qal[4][4];
    float m0 = -1e30f, m1 = -1e30f, l0 = 0.f, l1 = 0.f;
    float o[8][4];
    #pragma unroll
    for (int j = 0; j < 8; j++)
        #pragma unroll
        for (int u = 0; u < 4; u++) o[j][u] = 0.f;

    int q0g = qb + w * 16 + (lane >> 2);
    int q1g = q0g + 8;

    int ntiles = 2 * qt + 2;
    for (int kt = 0; kt < ntiles; kt++) {
        int k0 = kt * 64;
        if (kt + 1 < ntiles) {
            uint32_t bufb = 32768u + (uint32_t)((kt + 1) & 1) * 16384u;
            size_t ktok = (size_t)(b * SEQ + (kt + 1) * 64);
            #pragma unroll
            for (int i = 0; i < 4; i++) {
                int c = t + i * 256;
                int plane = c >> 9, rem = c & 511;
                int row = rem >> 3, u = rem & 7;
                uint32_t so = bufb + (uint32_t)(plane * 8192 + row * 128 + ((u ^ (row & 7)) << 4));
                const __half* gp = qkvh + (ktok + row) * QKV_M + 1024 + plane * 1024 + h * 64 + u * 8;
                cp16(sb + so, gp);
            }
            cp_commit();
            cp_wait1();
        } else {
            cp_wait0();
        }
        __syncthreads();

        if (kt == 0) {
            int arow = w * 16 + (lane & 15);
            uint32_t aro = (uint32_t)(arow * 128);
            uint32_t asw = (uint32_t)(arow & 7);
            #pragma unroll
            for (int ks = 0; ks < 4; ks++) {
                uint32_t u = (uint32_t)(ks * 2) + (uint32_t)(lane >> 4);
                uint32_t off = aro + ((u ^ asw) << 4);
                ldsm4(qah[ks], sb + off);
                ldsm4(qal[ks], sb + 16384 + off);
            }
        }

        uint32_t kvb = sb + 32768u + (uint32_t)(kt & 1) * 16384u;

        // ---- S = Q K^T (Q split, K single plane) ----
        float s[8][4];
        #pragma unroll
        for (int j = 0; j < 8; j++)
            #pragma unroll
            for (int u = 0; u < 4; u++) s[j][u] = 0.f;

        #pragma unroll
        for (int nh = 0; nh < 4; nh++) {
            int brow = nh * 16 + ((g >> 1) << 3) + l7;
            uint32_t bro = (uint32_t)(brow * 128);
            uint32_t bsw = (uint32_t)(brow & 7);
            #pragma unroll
            for (int ks = 0; ks < 4; ks++) {
                uint32_t u = (uint32_t)(ks * 2) + (uint32_t)(g & 1);
                uint32_t off = bro + ((u ^ bsw) << 4);
                uint32_t bhf[4];
                ldsm4(bhf, kvb + off);
                float* c0 = s[nh * 2];
                float* c1 = s[nh * 2 + 1];
                mma_f16(c0, qah[ks], bhf[0], bhf[1]);
                mma_f16(c0, qal[ks], bhf[0], bhf[1]);
                mma_f16(c1, qah[ks], bhf[2], bhf[3]);
                mma_f16(c1, qal[ks], bhf[2], bhf[3]);
            }
        }

        bool diag = (kt >= 2 * qt);
        float mx0 = -1e30f, mx1 = -1e30f;
        #pragma unroll
        for (int j = 0; j < 8; j++) {
            int kb = k0 + j * 8 + ((lane & 3) << 1);
            float y0 = s[j][0] * SCALE_L2E;
            float y1 = s[j][1] * SCALE_L2E;
            float y2 = s[j][2] * SCALE_L2E;
            float y3 = s[j][3] * SCALE_L2E;
            if (diag) {
                if (kb     > q0g) y0 = -1e30f;
                if (kb + 1 > q0g) y1 = -1e30f;
                if (kb     > q1g) y2 = -1e30f;
                if (kb + 1 > q1g) y3 = -1e30f;
            }
            s[j][0] = y0; s[j][1] = y1; s[j][2] = y2; s[j][3] = y3;
            mx0 = fmaxf(mx0, fmaxf(y0, y1));
            mx1 = fmaxf(mx1, fmaxf(y2, y3));
        }
        mx0 = fmaxf(mx0, __shfl_xor_sync(0xFFFFFFFFu, mx0, 1));
        mx0 = fmaxf(mx0, __shfl_xor_sync(0xFFFFFFFFu, mx0, 2));
        mx1 = fmaxf(mx1, __shfl_xor_sync(0xFFFFFFFFu, mx1, 1));
        mx1 = fmaxf(mx1, __shfl_xor_sync(0xFFFFFFFFu, mx1, 2));

        float m0n = fmaxf(m0, mx0), m1n = fmaxf(m1, mx1);
        float corr0 = fexp2(m0 - m0n), corr1 = fexp2(m1 - m1n);
        m0 = m0n; m1 = m1n;

        float rs0 = 0.f, rs1 = 0.f;
        #pragma unroll
        for (int j = 0; j < 8; j++) {
            float p0 = fexp2(s[j][0] - m0);
            float p1 = fexp2(s[j][1] - m0);
            float p2 = fexp2(s[j][2] - m1);
            float p3 = fexp2(s[j][3] - m1);
            s[j][0] = p0; s[j][1] = p1; s[j][2] = p2; s[j][3] = p3;
            rs0 += p0 + p1; rs1 += p2 + p3;
        }
        rs0 += __shfl_xor_sync(0xFFFFFFFFu, rs0, 1);
        rs0 += __shfl_xor_sync(0xFFFFFFFFu, rs0, 2);
        rs1 += __shfl_xor_sync(0xFFFFFFFFu, rs1, 1);
        rs1 += __shfl_xor_sync(0xFFFFFFFFu, rs1, 2);
        l0 = l0 * corr0 + rs0;
        l1 = l1 * corr1 + rs1;
        #pragma unroll
        for (int j = 0; j < 8; j++) {
            o[j][0] *= corr0; o[j][1] *= corr0;
            o[j][2] *= corr1; o[j][3] *= corr1;
        }

        // ---- O += P V (P split, V single plane) ----
        #pragma unroll
        for (int ks2 = 0; ks2 < 4; ks2++) {
            int j0 = ks2 * 2, j1 = j0 + 1;
            uint32_t aPh[4], aPl[4];
            aPh[0] = f2h2(s[j0][0], s[j0][1]);
            aPh[1] = f2h2(s[j0][2], s[j0][3]);
            aPh[2] = f2h2(s[j1][0], s[j1][1]);
            aPh[3] = f2h2(s[j1][2], s[j1][3]);
            {
                __half2* p0 = reinterpret_cast<__half2*>(&aPh[0]);
                __half2* p1 = reinterpret_cast<__half2*>(&aPh[1]);
                __half2* p2 = reinterpret_cast<__half2*>(&aPh[2]);
                __half2* p3 = reinterpret_cast<__half2*>(&aPh[3]);
                aPl[0] = f2h2(s[j0][0] - __low2float(*p0), s[j0][1] - __high2float(*p0));
                aPl[1] = f2h2(s[j0][2] - __low2float(*p1), s[j0][3] - __high2float(*p1));
                aPl[2] = f2h2(s[j1][0] - __low2float(*p2), s[j1][1] - __high2float(*p2));
                aPl[3] = f2h2(s[j1][2] - __low2float(*p3), s[j1][3] - __high2float(*p3));
            }

            int vrow = ks2 * 16 + ((g & 1) << 3) + l7;
            uint32_t vro = (uint32_t)(vrow * 128);
            uint32_t vsw = (uint32_t)(vrow & 7);
            #pragma unroll
            for (int dh = 0; dh < 4; dh++) {
                uint32_t u = (uint32_t)(dh * 2) + (uint32_t)(g >> 1);
                uint32_t off = vro + ((u ^ vsw) << 4);
                uint32_t vhf[4];
                ldsm4t(vhf, kvb + 8192 + off);
                float* c0 = o[dh * 2];
                float* c1 = o[dh * 2 + 1];
                mma_f16(c0, aPh, vhf[0], vhf[1]);
                mma_f16(c0, aPl, vhf[0], vhf[1]);
                mma_f16(c1, aPh, vhf[2], vhf[3]);
                mma_f16(c1, aPl, vhf[2], vhf[3]);
            }
        }
        __syncthreads();
    }

    float inv0 = 1.0f / l0, inv1 = 1.0f / l1;
    size_t r0o = ((size_t)(b * SEQ) + q0g) * DMODEL + h * 64;
    size_t r1o = ((size_t)(b * SEQ) + q1g) * DMODEL + h * 64;
    #pragma unroll
    for (int j = 0; j < 8; j++) {
        int col = j * 8 + (lane & 3) * 2;
        float v0 = o[j][0] * inv0, v1 = o[j][1] * inv0;
        float v2 = o[j][2] * inv1, v3 = o[j][3] * inv1;
        __half2 hp0 = __floats2half2_rn(v0, v1);
        __half2 lp0 = __floats2half2_rn(v0 - __low2float(hp0), v1 - __high2float(hp0));
        __half2 hp1 = __floats2half2_rn(v2, v3);
        __half2 lp1 = __floats2half2_rn(v2 - __low2float(hp1), v3 - __high2float(hp1));
        *reinterpret_cast<__half2*>(ohi + r0o + col) = hp0;
        *reinterpret_cast<__half2*>(olo + r0o + col) = lp0;
        *reinterpret_cast<__half2*>(ohi + r1o + col) = hp1;
        *reinterpret_cast<__half2*>(olo + r1o + col) = lp1;
    }
}

// ---------------- launch ----------------
extern "C" void kernel_launch(void* const* d_in, const int* in_sizes, int n_in,
                              void* d_out, int out_size) {
    const float* x    = (const float*)d_in[0];
    const float* ln1g = (const float*)d_in[1];
    const float* ln1b = (const float*)d_in[2];
    const float* Wq   = (const float*)d_in[3];
    const float* bq   = (const float*)d_in[4];
    const float* Wk   = (const float*)d_in[5];
    const float* bk   = (const float*)d_in[6];
    const float* Wv   = (const float*)d_in[7];
    const float* bv   = (const float*)d_in[8];
    const float* Wo   = (const float*)d_in[9];
    const float* bo   = (const float*)d_in[10];
    const float* ln2g = (const float*)d_in[11];
    const float* ln2b = (const float*)d_in[12];
    const float* W1   = (const float*)d_in[13];
    const float* b1   = (const float*)d_in[14];
    const float* W2   = (const float*)d_in[15];
    const float* b2   = (const float*)d_in[16];
    float* out = (float*)d_out;

    __half *w, *hh, *hl, *qkvh, *qkvl, *oh, *ol, *fh, *fl;
    float *x1, *b3;
    cudaGetSymbolAddress((void**)&w,    g_w);
    cudaGetSymbolAddress((void**)&hh,   g_hh);
    cudaGetSymbolAddress((void**)&hl,   g_hl);
    cudaGetSymbolAddress((void**)&qkvh, g_qkvh);
    cudaGetSymbolAddress((void**)&qkvl, g_qkvl);
    cudaGetSymbolAddress((void**)&oh,   g_oh);
    cudaGetSymbolAddress((void**)&ol,   g_ol);
    cudaGetSymbolAddress((void**)&fh,   g_fh);
    cudaGetSymbolAddress((void**)&fl,   g_fl);
    cudaGetSymbolAddress((void**)&x1,   g_x1);
    cudaGetSymbolAddress((void**)&b3,   g_b3);

    static int attr_set = 0;
    if (!attr_set) {
        cudaFuncSetAttribute(attn_mma, cudaFuncAttributeMaxDynamicSharedMemorySize, ATT_SMEM);
        cudaFuncSetAttribute(gemm_mma<0, 0, 1>, cudaFuncAttributeMaxDynamicSharedMemorySize, GEMM_SMEM);
        cudaFuncSetAttribute(gemm_mma<0, 1, 0>, cudaFuncAttributeMaxDynamicSharedMemorySize, GEMM_SMEM);
        cudaFuncSetAttribute(gemm_mma<1, 0, 1>, cudaFuncAttributeMaxDynamicSharedMemorySize, GEMM_SMEM);
        attr_set = 1;
    }

    wsplit_all<<<12288, 256>>>(Wq, Wk, Wv, Wo, W1, W2, w);
    biascat_kernel<<<12, 256>>>(bq, bk, bv, b3);

    // --- attention sublayer ---
    ln_kernel<<<N_TOK, 256>>>(x, ln1g, ln1b, hh, hl);
    gemm_mma<0, 0, 1><<<dim3(QKV_M / 128, 32), 256, GEMM_SMEM>>>(
        hh, hl, w + WQO, b3, nullptr, nullptr, qkvh, qkvl, DMODEL, QKV_M);
    attn_mma<<<dim3(SEQ / 128, NHEAD * BATCH), 256, ATT_SMEM>>>(qkvh, qkvl, oh, ol);
    gemm_mma<0, 1, 0><<<dim3(8, 32), 256, GEMM_SMEM>>>(
        oh, ol, w + WOO, bo, x, x1, nullptr, nullptr, DMODEL, DMODEL);

    // --- FFN sublayer ---
    ln_kernel<<<N_TOK, 256>>>(x1, ln2g, ln2b, hh, hl);
    gemm_mma<1, 0, 1><<<dim3(32, 32), 256, GEMM_SMEM>>>(
        hh, hl, w + W1O, b1, nullptr, nullptr, fh, fl, DMODEL, DFF);
    gemm_mma<0, 1, 0><<<dim3(8, 32), 256, GEMM_SMEM>>>(
        fh, fl, w + W2O, b2, x1, out, nullptr, nullptr, DFF, DMODEL);
}

// round 8
// speedup vs baseline: 9.4968x; 1.4349x over previous
#include <cuda_runtime.h>
#include <cuda_fp16.h>
#include <math.h>
#include <stdint.h>

#define N_TOK   4096     // B * S
#define DMODEL  1024
#define DFF     4096
#define NHEAD   16
#define DK      64
#define SEQ     2048
#define BATCH   2
#define QKV_M   3072

// ---------------- scratch (static device globals; no allocation) ----------------
#define WQO 0
#define WKO (1u << 20)
#define WVO (2u << 20)
#define WOO (3u << 20)
#define W1O (4u << 20)
#define W2O (8u << 20)
__device__ __half g_w  [12u << 20];                 // weights: fp16, [outfeat][K]
__device__ __half g_hh [N_TOK * DMODEL];            // LN out (single plane)
__device__ __half g_qkvh[(size_t)N_TOK * QKV_M];
__device__ __half g_qkvl[(size_t)N_TOK * QKV_M];    // lo plane (attention Q needs it)
__device__ __half g_oh [N_TOK * DMODEL];
__device__ __half g_fh [(size_t)N_TOK * DFF];
__device__ float g_x1[N_TOK * DMODEL];
__device__ float g_b3[QKV_M];

// ---------------- helpers ----------------
__device__ __forceinline__ uint32_t smem_u32(const void* p) {
    uint32_t a;
    asm("{ .reg .u64 t; cvta.to.shared.u64 t, %1; cvt.u32.u64 %0, t; }" : "=r"(a) : "l"(p));
    return a;
}
__device__ __forceinline__ void cp16(uint32_t s, const void* g) {
    asm volatile("cp.async.cg.shared.global [%0], [%1], 16;" :: "r"(s), "l"(g));
}
__device__ __forceinline__ void cp_commit() { asm volatile("cp.async.commit_group;"); }
__device__ __forceinline__ void cp_wait4()  { asm volatile("cp.async.wait_group 4;"); }
__device__ __forceinline__ void cp_wait1()  { asm volatile("cp.async.wait_group 1;"); }
__device__ __forceinline__ void cp_wait0()  { asm volatile("cp.async.wait_group 0;"); }
__device__ __forceinline__ void ldsm4(uint32_t* r, uint32_t addr) {
    asm volatile("ldmatrix.sync.aligned.m8n8.x4.shared.b16 {%0,%1,%2,%3}, [%4];"
                 : "=r"(r[0]), "=r"(r[1]), "=r"(r[2]), "=r"(r[3]) : "r"(addr));
}
__device__ __forceinline__ void ldsm4t(uint32_t* r, uint32_t addr) {
    asm volatile("ldmatrix.sync.aligned.m8n8.x4.trans.shared.b16 {%0,%1,%2,%3}, [%4];"
                 : "=r"(r[0]), "=r"(r[1]), "=r"(r[2]), "=r"(r[3]) : "r"(addr));
}
__device__ __forceinline__ void mma_f16(float* c, const uint32_t* a, uint32_t b0, uint32_t b1) {
    asm volatile("mma.sync.aligned.m16n8k16.row.col.f32.f16.f16.f32 "
                 "{%0,%1,%2,%3}, {%4,%5,%6,%7}, {%8,%9}, {%0,%1,%2,%3};"
                 : "+f"(c[0]), "+f"(c[1]), "+f"(c[2]), "+f"(c[3])
                 : "r"(a[0]), "r"(a[1]), "r"(a[2]), "r"(a[3]), "r"(b0), "r"(b1));
}
__device__ __forceinline__ uint32_t f2h2(float a, float b) {
    __half2 h = __floats2half2_rn(a, b);
    return *reinterpret_cast<uint32_t*>(&h);
}
// 2^y on the FMA pipe (y <= 0; clamped below -125). rel err ~1e-7.
__device__ __forceinline__ float fexp2(float y) {
    y = fmaxf(y, -125.f);
    float r = y + 12582912.f;
    float f = y - (r - 12582912.f);
    int n = __float_as_int(r) - 0x4B400000;
    float p = 0.0013333558f;
    p = fmaf(p, f, 0.0096181291f);
    p = fmaf(p, f, 0.055504109f);
    p = fmaf(p, f, 0.24022651f);
    p = fmaf(p, f, 0.69314718f);
    p = fmaf(p, f, 1.0f);
    return p * __int_as_float((n + 127) << 23);
}

// ---------------- LayerNorm (fp16 single-plane output) ----------------
__global__ void __launch_bounds__(256) ln_kernel(const float* __restrict__ x,
                                                 const float* __restrict__ gamma,
                                                 const float* __restrict__ beta,
                                                 __half* __restrict__ ohi) {
    int row = blockIdx.x;
    int t = threadIdx.x;
    const float4 v = reinterpret_cast<const float4*>(x + (size_t)row * DMODEL)[t];
    float s  = v.x + v.y + v.z + v.w;
    float sq = v.x * v.x + v.y * v.y + v.z * v.z + v.w * v.w;
    #pragma unroll
    for (int o = 16; o; o >>= 1) {
        s  += __shfl_xor_sync(0xFFFFFFFFu, s,  o);
        sq += __shfl_xor_sync(0xFFFFFFFFu, sq, o);
    }
    __shared__ float ss[8], ssq[8];
    __shared__ float s_mean, s_rstd;
    int wid = t >> 5, lane = t & 31;
    if (lane == 0) { ss[wid] = s; ssq[wid] = sq; }
    __syncthreads();
    if (t == 0) {
        float ts = 0.f, tq = 0.f;
        #pragma unroll
        for (int i = 0; i < 8; i++) { ts += ss[i]; tq += ssq[i]; }
        float mean = ts * (1.0f / DMODEL);
        float var  = tq * (1.0f / DMODEL) - mean * mean;
        s_mean = mean;
        s_rstd = rsqrtf(var + 1e-5f);
    }
    __syncthreads();
    float mean = s_mean, rstd = s_rstd;
    float4 g4 = reinterpret_cast<const float4*>(gamma)[t];
    float4 b4 = reinterpret_cast<const float4*>(beta)[t];
    float o0 = (v.x - mean) * rstd * g4.x + b4.x;
    float o1 = (v.y - mean) * rstd * g4.y + b4.y;
    float o2 = (v.z - mean) * rstd * g4.z + b4.z;
    float o3 = (v.w - mean) * rstd * g4.w + b4.w;
    size_t idx = (size_t)row * DMODEL + t * 4;
    *reinterpret_cast<__half2*>(ohi + idx)     = __floats2half2_rn(o0, o1);
    *reinterpret_cast<__half2*>(ohi + idx + 2) = __floats2half2_rn(o2, o3);
}

// ---------------- all-weights transpose + fp16 convert (single launch) ----------------
__global__ void __launch_bounds__(256) wsplit_all(const float* __restrict__ Wq,
                                                  const float* __restrict__ Wk,
                                                  const float* __restrict__ Wv,
                                                  const float* __restrict__ Wo,
                                                  const float* __restrict__ W1,
                                                  const float* __restrict__ W2,
                                                  __half* __restrict__ out) {
    __shared__ float tile[32][33];
    int id = blockIdx.x;
    const float* W;
    int K, M, n0, k0;
    uint32_t base;
    if (id < 4096) {
        int wsel = id >> 10, local = id & 1023;
        K = M = 1024;
        n0 = (local & 31) * 32; k0 = (local >> 5) * 32;
        W = (wsel == 0) ? Wq : (wsel == 1) ? Wk : (wsel == 2) ? Wv : Wo;
        base = (uint32_t)wsel << 20;
    } else if (id < 8192) {
        int local = id - 4096;
        K = 1024; M = 4096;
        n0 = (local & 127) * 32; k0 = (local >> 7) * 32;
        W = W1; base = W1O;
    } else {
        int local = id - 8192;
        K = 4096; M = 1024;
        n0 = (local & 31) * 32; k0 = (local >> 5) * 32;
        W = W2; base = W2O;
    }
    int tx = threadIdx.x & 31, ty = threadIdx.x >> 5;
    #pragma unroll
    for (int i = 0; i < 4; i++)
        tile[ty + 8 * i][tx] = W[(size_t)(k0 + ty + 8 * i) * M + n0 + tx];
    __syncthreads();
    #pragma unroll
    for (int i = 0; i < 4; i++) {
        float x = tile[tx][ty + 8 * i];
        out[(size_t)base + (size_t)(n0 + ty + 8 * i) * K + k0 + tx] = __float2half_rn(x);
    }
}

__global__ void biascat_kernel(const float* bq, const float* bk, const float* bv, float* out) {
    int i = blockIdx.x * 256 + threadIdx.x;
    float v = (i < 1024) ? bq[i] : (i < 2048) ? bk[i - 1024] : bv[i - 2048];
    out[i] = v;
}

// ---------------- mma.sync fp16 GEMM (single A plane, single B plane) ----------------
// 6-stage cp.async pipeline. Stage = A(8KB) + B(8KB) = 16KB; 6 stages = 96KB.
#define GEMM_SMEM (6 * 16384)

// SPLIT: 0 = fp32 out (+res), 1 = fp16 hi+lo planes, 2 = fp16 hi plane only
template<int GELU, int RES, int SPLIT>
__global__ void __launch_bounds__(256, 2) gemm_mma(const __half* __restrict__ Ah,
                                                   const __half* __restrict__ Bh,
                                                   const float* __restrict__ bias,
                                                   const float* __restrict__ res,
                                                   float* __restrict__ C,
                                                   __half* __restrict__ Chi,
                                                   __half* __restrict__ Clo,
                                                   int K, int M) {
    extern __shared__ char smc[];
    uint32_t sb = smem_u32(smc);
    int t = threadIdx.x, lane = t & 31, wid = t >> 5;
    int wr = wid & 3, wc = wid >> 2;
    int m0 = blockIdx.x * 128;
    size_t row0 = (size_t)blockIdx.y * 128;

    int r0 = t >> 2, cq = t & 3;
    int r1 = r0 + 64;
    uint32_t sO0 = (uint32_t)(r0 * 64 + ((cq ^ ((r0 >> 1) & 3)) << 4));
    uint32_t sO1 = (uint32_t)(r1 * 64 + ((cq ^ ((r1 >> 1) & 3)) << 4));
    const __half* gA0 = Ah + (row0 + r0) * (size_t)K + cq * 8;
    const __half* gA1 = Ah + (row0 + r1) * (size_t)K + cq * 8;
    const __half* gB0 = Bh + (size_t)(m0 + r0) * K + cq * 8;
    const __half* gB1 = Bh + (size_t)(m0 + r1) * K + cq * 8;

    int g = lane >> 3, l7 = lane & 7;
    int arow0 = wr * 32 + l7 + ((g & 1) << 3);
    int arow1 = arow0 + 16;
    uint32_t aRO0 = (uint32_t)(arow0 * 64), aSW0 = (uint32_t)((arow0 >> 1) & 3);
    uint32_t aRO1 = (uint32_t)(arow1 * 64), aSW1 = (uint32_t)((arow1 >> 1) & 3);
    uint32_t aKH = (uint32_t)(g >> 1);
    int brow_base = wc * 64 + ((g >> 1) << 3) + l7;
    uint32_t bKH = (uint32_t)(g & 1);

    float acc[2][8][4];
    #pragma unroll
    for (int i = 0; i < 2; i++)
        #pragma unroll
        for (int j = 0; j < 8; j++)
            #pragma unroll
            for (int u = 0; u < 4; u++) acc[i][j][u] = 0.f;

    int NC = K >> 5;

    // prologue: chunks 0..4 -> stages 0..4
    #pragma unroll
    for (int pk = 0; pk < 5; pk++) {
        uint32_t bb = sb + (uint32_t)pk * 16384u;
        int ko = pk * 32;
        cp16(bb + sO0,        gA0 + ko); cp16(bb + sO1,        gA1 + ko);
        cp16(bb + 8192 + sO0, gB0 + ko); cp16(bb + 8192 + sO1, gB1 + ko);
        cp_commit();
    }

    int stage = 0, nstage = 5;
    for (int kt = 0; kt < NC; kt++) {
        cp_wait4();           // chunk kt complete (kt+1..kt+4 may be in flight)
        __syncthreads();

        if (kt + 5 < NC) {
            uint32_t bb = sb + (uint32_t)nstage * 16384u;
            int ko = (kt + 5) * 32;
            cp16(bb + sO0,        gA0 + ko); cp16(bb + sO1,        gA1 + ko);
            cp16(bb + 8192 + sO0, gB0 + ko); cp16(bb + 8192 + sO1, gB1 + ko);
        }
        cp_commit();

        uint32_t bb = sb + (uint32_t)stage * 16384u;
        #pragma unroll
        for (int ks = 0; ks < 2; ks++) {
            uint32_t ac = (uint32_t)(ks * 2) + aKH;
            uint32_t ah0[4], ah1[4];
            ldsm4(ah0, bb + aRO0 + ((ac ^ aSW0) << 4));
            ldsm4(ah1, bb + aRO1 + ((ac ^ aSW1) << 4));
            #pragma unroll
            for (int nh = 0; nh < 4; nh++) {
                int brow = brow_base + nh * 16;
                uint32_t bRO = (uint32_t)(brow * 64), bSW = (uint32_t)((brow >> 1) & 3);
                uint32_t bc = (uint32_t)(ks * 2) + bKH;
                uint32_t boff = bRO + ((bc ^ bSW) << 4);
                uint32_t bh[4];
                ldsm4(bh, bb + 8192 + boff);
                #pragma unroll
                for (int s = 0; s < 2; s++) {
                    mma_f16(acc[0][nh * 2 + s], ah0, bh[s * 2], bh[s * 2 + 1]);
                    mma_f16(acc[1][nh * 2 + s], ah1, bh[s * 2], bh[s * 2 + 1]);
                }
            }
        }
        stage = (stage == 5) ? 0 : stage + 1;
        nstage = (nstage == 5) ? 0 : nstage + 1;
    }

    #pragma unroll
    for (int mt = 0; mt < 2; mt++) {
        size_t rbase = row0 + wr * 32 + mt * 16 + (lane >> 2);
        #pragma unroll
        for (int nt = 0; nt < 8; nt++) {
            int col = m0 + wc * 64 + nt * 8 + (lane & 3) * 2;
            float b0 = bias[col], b1 = bias[col + 1];
            #pragma unroll
            for (int half = 0; half < 2; half++) {
                size_t row = rbase + half * 8;
                float v0 = acc[mt][nt][half * 2 + 0] + b0;
                float v1 = acc[mt][nt][half * 2 + 1] + b1;
                if (GELU) { v0 = v0 * normcdff(v0); v1 = v1 * normcdff(v1); }
                if (RES) {
                    float2 r2 = *reinterpret_cast<const float2*>(res + row * M + col);
                    v0 += r2.x; v1 += r2.y;
                }
                if (SPLIT == 1) {
                    __half2 hp = __floats2half2_rn(v0, v1);
                    __half2 lp = __floats2half2_rn(v0 - __low2float(hp),
                                                   v1 - __high2float(hp));
                    *reinterpret_cast<__half2*>(Chi + row * M + col) = hp;
                    *reinterpret_cast<__half2*>(Clo + row * M + col) = lp;
                } else if (SPLIT == 2) {
                    *reinterpret_cast<__half2*>(Chi + row * M + col) = __floats2half2_rn(v0, v1);
                } else {
                    *reinterpret_cast<float2*>(C + row * M + col) = make_float2(v0, v1);
                }
            }
        }
    }
}

// ---------------- mma.sync causal flash attention (fp16, unchanged compute) ----------------
// smem: Qh [128][64] @0 (16KB), Ql @16384 (16KB); KV stages @32768: 2 x (Kh 8KB + Vh 8KB).
#define ATT_SMEM 65536
#define SCALE_L2E 0.18033688f   // 0.125 * log2(e)

__global__ void __launch_bounds__(256) attn_mma(const __half* __restrict__ qkvh,
                                                const __half* __restrict__ qkvl,
                                                __half* __restrict__ ohi) {
    extern __shared__ char smc[];
    uint32_t sb = smem_u32(smc);
    int t = threadIdx.x, lane = t & 31, w = t >> 5;
    int g = lane >> 3, l7 = lane & 7;
    int bh = blockIdx.y;
    int b = bh >> 4, h = bh & 15;
    int qt = (SEQ / 128 - 1) - blockIdx.x;
    int qb = qt * 128;
    size_t tok0 = (size_t)(b * SEQ + qb);

    {
        #pragma unroll
        for (int i = 0; i < 8; i++) {
            int c = t + i * 256;
            int plane = c >> 10, rem = c & 1023;
            int row = rem >> 3, u = rem & 7;
            uint32_t so = (uint32_t)(plane * 16384 + row * 128 + ((u ^ (row & 7)) << 4));
            const __half* gp = (plane ? qkvl : qkvh) + (tok0 + row) * QKV_M + h * 64 + u * 8;
            cp16(sb + so, gp);
        }
        size_t ktok = (size_t)(b * SEQ);
        #pragma unroll
        for (int i = 0; i < 4; i++) {
            int c = t + i * 256;
            int plane = c >> 9, rem = c & 511;   // 0=K, 1=V
            int row = rem >> 3, u = rem & 7;
            uint32_t so = (uint32_t)(32768 + plane * 8192 + row * 128 + ((u ^ (row & 7)) << 4));
            const __half* gp = qkvh + (ktok + row) * QKV_M + 1024 + plane * 1024 + h * 64 + u * 8;
            cp16(sb + so, gp);
        }
        cp_commit();
    }

    uint32_t qah[4][4], qal[4][4];
    float m0 = -1e30f, m1 = -1e30f, l0 = 0.f, l1 = 0.f;
    float o[8][4];
    #pragma unroll
    for (int j = 0; j < 8; j++)
        #pragma unroll
        for (int u = 0; u < 4; u++) o[j][u] = 0.f;

    int q0g = qb + w * 16 + (lane >> 2);
    int q1g = q0g + 8;

    int ntiles = 2 * qt + 2;
    for (int kt = 0; kt < ntiles; kt++) {
        int k0 = kt * 64;
        if (kt + 1 < ntiles) {
            uint32_t bufb = 32768u + (uint32_t)((kt + 1) & 1) * 16384u;
            size_t ktok = (size_t)(b * SEQ + (kt + 1) * 64);
            #pragma unroll
            for (int i = 0; i < 4; i++) {
                int c = t + i * 256;
                int plane = c >> 9, rem = c & 511;
                int row = rem >> 3, u = rem & 7;
                uint32_t so = bufb + (uint32_t)(plane * 8192 + row * 128 + ((u ^ (row & 7)) << 4));
                const __half* gp = qkvh + (ktok + row) * QKV_M + 1024 + plane * 1024 + h * 64 + u * 8;
                cp16(sb + so, gp);
            }
            cp_commit();
            cp_wait1();
        } else {
            cp_wait0();
        }
        __syncthreads();

        if (kt == 0) {
            int arow = w * 16 + (lane & 15);
            uint32_t aro = (uint32_t)(arow * 128);
            uint32_t asw = (uint32_t)(arow & 7);
            #pragma unroll
            for (int ks = 0; ks < 4; ks++) {
                uint32_t u = (uint32_t)(ks * 2) + (uint32_t)(lane >> 4);
                uint32_t off = aro + ((u ^ asw) << 4);
                ldsm4(qah[ks], sb + off);
                ldsm4(qal[ks], sb + 16384 + off);
            }
        }

        uint32_t kvb = sb + 32768u + (uint32_t)(kt & 1) * 16384u;

        float s[8][4];
        #pragma unroll
        for (int j = 0; j < 8; j++)
            #pragma unroll
            for (int u = 0; u < 4; u++) s[j][u] = 0.f;

        #pragma unroll
        for (int nh = 0; nh < 4; nh++) {
            int brow = nh * 16 + ((g >> 1) << 3) + l7;
            uint32_t bro = (uint32_t)(brow * 128);
            uint32_t bsw = (uint32_t)(brow & 7);
            #pragma unroll
            for (int ks = 0; ks < 4; ks++) {
                uint32_t u = (uint32_t)(ks * 2) + (uint32_t)(g & 1);
                uint32_t off = bro + ((u ^ bsw) << 4);
                uint32_t bhf[4];
                ldsm4(bhf, kvb + off);
                float* c0 = s[nh * 2];
                float* c1 = s[nh * 2 + 1];
                mma_f16(c0, qah[ks], bhf[0], bhf[1]);
                mma_f16(c0, qal[ks], bhf[0], bhf[1]);
                mma_f16(c1, qah[ks], bhf[2], bhf[3]);
                mma_f16(c1, qal[ks], bhf[2], bhf[3]);
            }
        }

        bool diag = (kt >= 2 * qt);
        float mx0 = -1e30f, mx1 = -1e30f;
        #pragma unroll
        for (int j = 0; j < 8; j++) {
            int kb = k0 + j * 8 + ((lane & 3) << 1);
            float y0 = s[j][0] * SCALE_L2E;
            float y1 = s[j][1] * SCALE_L2E;
            float y2 = s[j][2] * SCALE_L2E;
            float y3 = s[j][3] * SCALE_L2E;
            if (diag) {
                if (kb     > q0g) y0 = -1e30f;
                if (kb + 1 > q0g) y1 = -1e30f;
                if (kb     > q1g) y2 = -1e30f;
                if (kb + 1 > q1g) y3 = -1e30f;
            }
            s[j][0] = y0; s[j][1] = y1; s[j][2] = y2; s[j][3] = y3;
            mx0 = fmaxf(mx0, fmaxf(y0, y1));
            mx1 = fmaxf(mx1, fmaxf(y2, y3));
        }
        mx0 = fmaxf(mx0, __shfl_xor_sync(0xFFFFFFFFu, mx0, 1));
        mx0 = fmaxf(mx0, __shfl_xor_sync(0xFFFFFFFFu, mx0, 2));
        mx1 = fmaxf(mx1, __shfl_xor_sync(0xFFFFFFFFu, mx1, 1));
        mx1 = fmaxf(mx1, __shfl_xor_sync(0xFFFFFFFFu, mx1, 2));

        float m0n = fmaxf(m0, mx0), m1n = fmaxf(m1, mx1);
        float corr0 = fexp2(m0 - m0n), corr1 = fexp2(m1 - m1n);
        m0 = m0n; m1 = m1n;

        float rs0 = 0.f, rs1 = 0.f;
        #pragma unroll
        for (int j = 0; j < 8; j++) {
            float p0 = fexp2(s[j][0] - m0);
            float p1 = fexp2(s[j][1] - m0);
            float p2 = fexp2(s[j][2] - m1);
            float p3 = fexp2(s[j][3] - m1);
            s[j][0] = p0; s[j][1] = p1; s[j][2] = p2; s[j][3] = p3;
            rs0 += p0 + p1; rs1 += p2 + p3;
        }
        rs0 += __shfl_xor_sync(0xFFFFFFFFu, rs0, 1);
        rs0 += __shfl_xor_sync(0xFFFFFFFFu, rs0, 2);
        rs1 += __shfl_xor_sync(0xFFFFFFFFu, rs1, 1);
        rs1 += __shfl_xor_sync(0xFFFFFFFFu, rs1, 2);
        l0 = l0 * corr0 + rs0;
        l1 = l1 * corr1 + rs1;
        #pragma unroll
        for (int j = 0; j < 8; j++) {
            o[j][0] *= corr0; o[j][1] *= corr0;
            o[j][2] *= corr1; o[j][3] *= corr1;
        }

        #pragma unroll
        for (int ks2 = 0; ks2 < 4; ks2++) {
            int j0 = ks2 * 2, j1 = j0 + 1;
            uint32_t aPh[4], aPl[4];
            aPh[0] = f2h2(s[j0][0], s[j0][1]);
            aPh[1] = f2h2(s[j0][2], s[j0][3]);
            aPh[2] = f2h2(s[j1][0], s[j1][1]);
            aPh[3] = f2h2(s[j1][2], s[j1][3]);
            {
                __half2* p0 = reinterpret_cast<__half2*>(&aPh[0]);
                __half2* p1 = reinterpret_cast<__half2*>(&aPh[1]);
                __half2* p2 = reinterpret_cast<__half2*>(&aPh[2]);
                __half2* p3 = reinterpret_cast<__half2*>(&aPh[3]);
                aPl[0] = f2h2(s[j0][0] - __low2float(*p0), s[j0][1] - __high2float(*p0));
                aPl[1] = f2h2(s[j0][2] - __low2float(*p1), s[j0][3] - __high2float(*p1));
                aPl[2] = f2h2(s[j1][0] - __low2float(*p2), s[j1][1] - __high2float(*p2));
                aPl[3] = f2h2(s[j1][2] - __low2float(*p3), s[j1][3] - __high2float(*p3));
            }

            int vrow = ks2 * 16 + ((g & 1) << 3) + l7;
            uint32_t vro = (uint32_t)(vrow * 128);
            uint32_t vsw = (uint32_t)(vrow & 7);
            #pragma unroll
            for (int dh = 0; dh < 4; dh++) {
                uint32_t u = (uint32_t)(dh * 2) + (uint32_t)(g >> 1);
                uint32_t off = vro + ((u ^ vsw) << 4);
                uint32_t vhf[4];
                ldsm4t(vhf, kvb + 8192 + off);
                float* c0 = o[dh * 2];
                float* c1 = o[dh * 2 + 1];
                mma_f16(c0, aPh, vhf[0], vhf[1]);
                mma_f16(c0, aPl, vhf[0], vhf[1]);
                mma_f16(c1, aPh, vhf[2], vhf[3]);
                mma_f16(c1, aPl, vhf[2], vhf[3]);
            }
        }
        __syncthreads();
    }

    float inv0 = 1.0f / l0, inv1 = 1.0f / l1;
    size_t r0o = ((size_t)(b * SEQ) + q0g) * DMODEL + h * 64;
    size_t r1o = ((size_t)(b * SEQ) + q1g) * DMODEL + h * 64;
    #pragma unroll
    for (int j = 0; j < 8; j++) {
        int col = j * 8 + (lane & 3) * 2;
        *reinterpret_cast<__half2*>(ohi + r0o + col) =
            __floats2half2_rn(o[j][0] * inv0, o[j][1] * inv0);
        *reinterpret_cast<__half2*>(ohi + r1o + col) =
            __floats2half2_rn(o[j][2] * inv1, o[j][3] * inv1);
    }
}

// ---------------- launch ----------------
extern "C" void kernel_launch(void* const* d_in, const int* in_sizes, int n_in,
                              void* d_out, int out_size) {
    const float* x    = (const float*)d_in[0];
    const float* ln1g = (const float*)d_in[1];
    const float* ln1b = (const float*)d_in[2];
    const float* Wq   = (const float*)d_in[3];
    const float* bq   = (const float*)d_in[4];
    const float* Wk   = (const float*)d_in[5];
    const float* bk   = (const float*)d_in[6];
    const float* Wv   = (const float*)d_in[7];
    const float* bv   = (const float*)d_in[8];
    const float* Wo   = (const float*)d_in[9];
    const float* bo   = (const float*)d_in[10];
    const float* ln2g = (const float*)d_in[11];
    const float* ln2b = (const float*)d_in[12];
    const float* W1   = (const float*)d_in[13];
    const float* b1   = (const float*)d_in[14];
    const float* W2   = (const float*)d_in[15];
    const float* b2   = (const float*)d_in[16];
    float* out = (float*)d_out;

    __half *w, *hh, *qkvh, *qkvl, *oh, *fh;
    float *x1, *b3;
    cudaGetSymbolAddress((void**)&w,    g_w);
    cudaGetSymbolAddress((void**)&hh,   g_hh);
    cudaGetSymbolAddress((void**)&qkvh, g_qkvh);
    cudaGetSymbolAddress((void**)&qkvl, g_qkvl);
    cudaGetSymbolAddress((void**)&oh,   g_oh);
    cudaGetSymbolAddress((void**)&fh,   g_fh);
    cudaGetSymbolAddress((void**)&x1,   g_x1);
    cudaGetSymbolAddress((void**)&b3,   g_b3);

    static int attr_set = 0;
    if (!attr_set) {
        cudaFuncSetAttribute(attn_mma, cudaFuncAttributeMaxDynamicSharedMemorySize, ATT_SMEM);
        cudaFuncSetAttribute(gemm_mma<0, 0, 1>, cudaFuncAttributeMaxDynamicSharedMemorySize, GEMM_SMEM);
        cudaFuncSetAttribute(gemm_mma<0, 1, 0>, cudaFuncAttributeMaxDynamicSharedMemorySize, GEMM_SMEM);
        cudaFuncSetAttribute(gemm_mma<1, 0, 2>, cudaFuncAttributeMaxDynamicSharedMemorySize, GEMM_SMEM);
        attr_set = 1;
    }

    wsplit_all<<<12288, 256>>>(Wq, Wk, Wv, Wo, W1, W2, w);
    biascat_kernel<<<12, 256>>>(bq, bk, bv, b3);

    // --- attention sublayer ---
    ln_kernel<<<N_TOK, 256>>>(x, ln1g, ln1b, hh);
    gemm_mma<0, 0, 1><<<dim3(QKV_M / 128, 32), 256, GEMM_SMEM>>>(
        hh, w + WQO, b3, nullptr, nullptr, qkvh, qkvl, DMODEL, QKV_M);
    attn_mma<<<dim3(SEQ / 128, NHEAD * BATCH), 256, ATT_SMEM>>>(qkvh, qkvl, oh);
    gemm_mma<0, 1, 0><<<dim3(8, 32), 256, GEMM_SMEM>>>(
        oh, w + WOO, bo, x, x1, nullptr, nullptr, DMODEL, DMODEL);

    // --- FFN sublayer ---
    ln_kernel<<<N_TOK, 256>>>(x1, ln2g, ln2b, hh);
    gemm_mma<1, 0, 2><<<dim3(32, 32), 256, GEMM_SMEM>>>(
        hh, w + W1O, b1, nullptr, nullptr, fh, nullptr, DMODEL, DFF);
    gemm_mma<0, 1, 0><<<dim3(8, 32), 256, GEMM_SMEM>>>(
        fh, w + W2O, b2, x1, out, nullptr, nullptr, DFF, DMODEL);
}